// round 10
// baseline (speedup 1.0000x reference)
#include <cuda_runtime.h>
#include <cuda_bf16.h>
#include <cstdint>

// ---------------- problem constants ----------------
#define BB   4
#define TT   1024
#define CC   1024
#define NH   16
#define NKV  4
#define HD   64
#define EE   8
#define FF   4096
#define WIN  256
#define NTOK (BB*TT)          // 4096
#define EPS  1e-6f

// ---------------- scratch ----------------
__device__ float g_hn  [(size_t)NTOK*CC];
__device__ float g_q   [(size_t)NTOK*NH*HD];
__device__ float g_k   [(size_t)NTOK*NKV*HD];
__device__ float g_v   [(size_t)NTOK*NKV*HD];
__device__ float g_att [(size_t)NTOK*CC];
__device__ float g_hres[(size_t)NTOK*CC];
__device__ float g_gbuf[(size_t)NTOK*CC];
__device__ int   g_counts[EE];
__device__ int   g_tok [(size_t)EE*NTOK];
__device__ int   g_tidx[(size_t)NTOK*2];
__device__ int   g_tpos[(size_t)NTOK*2];
__device__ float g_twt [(size_t)NTOK*2];
__device__ float g_moe [(size_t)EE*NTOK*CC];
__device__ unsigned short g_gb16 [(size_t)NTOK*CC];
__device__ unsigned short g_hid16[(size_t)EE*NTOK*FF];
__device__ unsigned short g_w1t  [(size_t)EE*CC*FF];    // [e][FF][CC] bf16
__device__ unsigned short g_w3t  [(size_t)EE*CC*FF];
__device__ unsigned short g_w2t  [(size_t)EE*FF*CC];    // [e][CC][FF] bf16

// ---------------- helpers ----------------
__device__ __forceinline__ uint32_t smem_u32(const void* p) {
    uint32_t a;
    asm("{ .reg .u64 t; cvta.to.shared.u64 t, %1; cvt.u32.u64 %0, t; }" : "=r"(a) : "l"(p));
    return a;
}
__device__ __forceinline__ void cp16(uint32_t dst, const void* src) {
    asm volatile("cp.async.cg.shared.global [%0], [%1], 16;" :: "r"(dst), "l"(src));
}
__device__ __forceinline__ void cp_commit() { asm volatile("cp.async.commit_group;" ::: "memory"); }
__device__ __forceinline__ void cp_wait1() { asm volatile("cp.async.wait_group 1;" ::: "memory"); }
__device__ __forceinline__ void cp_wait2() { asm volatile("cp.async.wait_group 2;" ::: "memory"); }
__device__ __forceinline__ uint32_t f2tf(float f) {
    uint32_t r; asm("cvt.rna.tf32.f32 %0, %1;" : "=r"(r) : "f"(f)); return r;
}
__device__ __forceinline__ void mma8(float* c, const uint32_t* a, const uint32_t* b) {
    asm volatile("mma.sync.aligned.m16n8k8.row.col.f32.tf32.tf32.f32 "
                 "{%0,%1,%2,%3}, {%4,%5,%6,%7}, {%8,%9}, {%0,%1,%2,%3};"
                 : "+f"(c[0]), "+f"(c[1]), "+f"(c[2]), "+f"(c[3])
                 : "r"(a[0]), "r"(a[1]), "r"(a[2]), "r"(a[3]), "r"(b[0]), "r"(b[1]));
}
__device__ __forceinline__ void mma16(float* c, const uint32_t* a, const uint32_t* b) {
    asm volatile("mma.sync.aligned.m16n8k16.row.col.f32.bf16.bf16.f32 "
                 "{%0,%1,%2,%3}, {%4,%5,%6,%7}, {%8,%9}, {%0,%1,%2,%3};"
                 : "+f"(c[0]), "+f"(c[1]), "+f"(c[2]), "+f"(c[3])
                 : "r"(a[0]), "r"(a[1]), "r"(a[2]), "r"(a[3]), "r"(b[0]), "r"(b[1]));
}
__device__ __forceinline__ void ldsm4(uint32_t* r, uint32_t addr) {
    asm volatile("ldmatrix.sync.aligned.m8n8.x4.shared.b16 {%0,%1,%2,%3}, [%4];"
                 : "=r"(r[0]), "=r"(r[1]), "=r"(r[2]), "=r"(r[3]) : "r"(addr));
}

// ================= tf32 GEMM core (attention path) =================
#define NSTG 3
#define ASTRIDE 36
#define BSTRIDE 136
#define ASZ (128*ASTRIDE)
#define BSZ (32*BSTRIDE)
#define SMEMG (NSTG*(ASZ+BSZ)*4)   // 107520 bytes

__device__ __forceinline__ void gemm_body_tf32(
    const float* __restrict__ A, int m0,
    const float* __restrict__ W, float* __restrict__ C, const float* __restrict__ res,
    int K, int Nw, int nloc, float* smf)
{
    float* Abuf[NSTG];
    float* Bbuf[NSTG];
    #pragma unroll
    for (int s = 0; s < NSTG; s++) {
        Abuf[s] = smf + s * ASZ;
        Bbuf[s] = smf + NSTG * ASZ + s * BSZ;
    }
    int tid = threadIdx.x;
    int lane = tid & 31, warp = tid >> 5;
    int wm = warp & 3, wn = warp >> 2;

    int ar = tid >> 1;
    int af = (tid & 1) * 4;
    const float* arow = A + (size_t)(m0 + ar) * K;
    int bk = tid >> 3;
    int bf = tid & 7;
    const float* brow = W + (size_t)bk * Nw + nloc + bf * 4;

    uint32_t aD[NSTG], bD[NSTG];
    #pragma unroll
    for (int p = 0; p < NSTG; p++) {
        aD[p] = smem_u32(Abuf[p]) + (ar * ASTRIDE + af * 4) * 4;
        bD[p] = smem_u32(Bbuf[p]) + (bk * BSTRIDE + bf * 4) * 4;
    }

    auto load_chunk = [&](int ci, int p) {
        const float* as = arow + ci * 32 + af * 4;
        #pragma unroll
        for (int j = 0; j < 4; j++) cp16(aD[p] + j * 16, as + j * 4);
        const float* bs = brow + (size_t)ci * 32 * Nw;
        #pragma unroll
        for (int j = 0; j < 4; j++) cp16(bD[p] + j * 128, bs + j * 32);
    };

    float acc[2][8][4];
    #pragma unroll
    for (int mi = 0; mi < 2; mi++)
        #pragma unroll
        for (int ni = 0; ni < 8; ni++)
            #pragma unroll
            for (int q = 0; q < 4; q++) acc[mi][ni][q] = 0.f;

    int lr = lane >> 2, lc = lane & 3;

    auto compute = [&](int p) {
        const float* Am = Abuf[p];
        const float* Bm = Bbuf[p];
        #pragma unroll
        for (int kk = 0; kk < 4; kk++) {
            int kb = kk * 8;
            uint32_t a[2][4], b[8][2];
            #pragma unroll
            for (int mi = 0; mi < 2; mi++) {
                const float* ap = Am + (wm * 32 + mi * 16 + lr) * ASTRIDE + kb + lc;
                a[mi][0] = f2tf(ap[0]);
                a[mi][1] = f2tf(ap[8 * ASTRIDE]);
                a[mi][2] = f2tf(ap[4]);
                a[mi][3] = f2tf(ap[8 * ASTRIDE + 4]);
            }
            #pragma unroll
            for (int ni = 0; ni < 8; ni++) {
                const float* bp = Bm + (kb + lc) * BSTRIDE + wn * 64 + ni * 8 + lr;
                b[ni][0] = f2tf(bp[0]);
                b[ni][1] = f2tf(bp[4 * BSTRIDE]);
            }
            #pragma unroll
            for (int mi = 0; mi < 2; mi++)
                #pragma unroll
                for (int ni = 0; ni < 8; ni++)
                    mma8(acc[mi][ni], a[mi], b[ni]);
        }
    };

    int NC = K / 32;
    load_chunk(0, 0); cp_commit();
    load_chunk(1, 1); cp_commit();
    for (int i = 0; i < NC; i++) {
        cp_wait1();
        __syncthreads();
        int nx = i + NSTG - 1;
        if (nx < NC) load_chunk(nx, nx % NSTG);
        cp_commit();
        compute(i % NSTG);
    }

    int tc = (lane & 3) * 2;
    #pragma unroll
    for (int mi = 0; mi < 2; mi++) {
        #pragma unroll
        for (int half = 0; half < 2; half++) {
            int m = m0 + wm * 32 + mi * 16 + half * 8 + lr;
            float* crow = C + (size_t)m * Nw + nloc + wn * 64;
            #pragma unroll
            for (int ni = 0; ni < 8; ni++) {
                float c0 = acc[mi][ni][half * 2 + 0];
                float c1 = acc[mi][ni][half * 2 + 1];
                if (res) {
                    const float2 rr = *(const float2*)(res + (size_t)m * Nw + nloc + wn * 64 + ni * 8 + tc);
                    c0 += rr.x; c1 += rr.y;
                }
                float2 v; v.x = c0; v.y = c1;
                *(float2*)(crow + ni * 8 + tc) = v;
            }
        }
    }
}

__global__ __launch_bounds__(256, 2)
void wo_gemm(const float* __restrict__ A, const float* __restrict__ W,
             float* __restrict__ C, const float* __restrict__ res)
{
    extern __shared__ float smf[];
    gemm_body_tf32(A, blockIdx.y * 128, W, C, res, CC, CC, blockIdx.x * 128, smf);
}

__global__ __launch_bounds__(256, 2)
void qkv_gemm(const float* __restrict__ hn,
              const float* __restrict__ wq, const float* __restrict__ wk,
              const float* __restrict__ wv)
{
    extern __shared__ float smf[];
    int m0 = blockIdx.y * 128;
    int nb = blockIdx.x;
    const float* W; float* O; int Nw, nloc;
    if (nb < 8)       { W = wq; O = g_q; Nw = NH * HD;  nloc = nb * 128; }
    else if (nb < 10) { W = wk; O = g_k; Nw = NKV * HD; nloc = (nb - 8) * 128; }
    else              { W = wv; O = g_v; Nw = NKV * HD; nloc = (nb - 10) * 128; }
    gemm_body_tf32(hn, m0, W, O, (const float*)0, CC, Nw, nloc, smf);
}

// ================= bf16 GEMM core (MoE path, ldmatrix) =================
#define HROW 80
#define HTILE_B (128*HROW)
#define NS16 4
#define SMEM16 (NS16*2*HTILE_B)    // 81920 bytes

struct Bf16Loop {
    uint32_t sbase;
    int lane, wm, wn;
    uint32_t aR, aK, bR, bK;
    __device__ __forceinline__ void init(uint32_t sb, int tid) {
        sbase = sb;
        lane = tid & 31;
        int warp = tid >> 5;
        wm = warp & 3; wn = warp >> 2;
        aR = (lane & 7) + ((lane >> 3) & 1) * 8;
        aK = ((lane >> 4) & 1) * 16;
        bR = (lane & 7) + ((lane >> 4) & 1) * 8;
        bK = ((lane >> 3) & 1) * 16;
    }
    __device__ __forceinline__ void compute(int p, float acc[2][8][4]) {
        uint32_t Am = sbase + p * (2 * HTILE_B);
        uint32_t Bm = Am + HTILE_B;
        #pragma unroll
        for (int kk = 0; kk < 2; kk++) {
            uint32_t a[2][4], b[4][4];
            #pragma unroll
            for (int mi = 0; mi < 2; mi++)
                ldsm4(a[mi], Am + (wm * 32 + mi * 16 + aR) * HROW + kk * 32 + aK);
            #pragma unroll
            for (int p2 = 0; p2 < 4; p2++)
                ldsm4(b[p2], Bm + (wn * 64 + p2 * 16 + bR) * HROW + kk * 32 + bK);
            #pragma unroll
            for (int mi = 0; mi < 2; mi++)
                #pragma unroll
                for (int ni = 0; ni < 8; ni++)
                    mma16(acc[mi][ni], a[mi], &b[ni >> 1][(ni & 1) * 2]);
        }
    }
};

// ---- fused MoE pass 1+2:  m-block = blockIdx.x (fastest) for L2 weight reuse ----
__global__ __launch_bounds__(256, 2)
void moe13_fused()
{
    int e = blockIdx.z;
    int cnt = g_counts[e];
    int m0 = blockIdx.x * 128;
    if (m0 >= cnt) return;
    int c0 = blockIdx.y * 64;

    extern __shared__ char smraw[];
    int tid = threadIdx.x;
    uint32_t sbase = smem_u32(smraw);
    Bf16Loop L; L.init(sbase, tid);

    int row = tid >> 1, sl = (tid & 1) * 2;
    const unsigned short* arow;
    {
        int grow = m0 + row;
        int g2 = (grow < cnt) ? grow : 0;
        arow = g_gb16 + (size_t)g_tok[e * NTOK + g2] * CC;
    }
    const unsigned short* brow = (row < 64)
        ? g_w1t + (size_t)e * CC * FF + (size_t)(c0 + row) * CC
        : g_w3t + (size_t)e * CC * FF + (size_t)(c0 + row - 64) * CC;

    uint32_t aD[NS16], bD[NS16];
    #pragma unroll
    for (int s = 0; s < NS16; s++) {
        aD[s] = sbase + s * (2 * HTILE_B) + row * HROW + sl * 16;
        bD[s] = aD[s] + HTILE_B;
    }
    auto load_chunk = [&](int ci, int p) {
        const unsigned short* as = arow + ci * 32 + sl * 8;
        cp16(aD[p], as); cp16(aD[p] + 16, as + 8);
        const unsigned short* bs = brow + ci * 32 + sl * 8;
        cp16(bD[p], bs); cp16(bD[p] + 16, bs + 8);
    };

    float acc[2][8][4];
    #pragma unroll
    for (int mi = 0; mi < 2; mi++)
        #pragma unroll
        for (int ni = 0; ni < 8; ni++)
            #pragma unroll
            for (int q = 0; q < 4; q++) acc[mi][ni][q] = 0.f;

    const int NC = CC / 32;
    load_chunk(0, 0); cp_commit();
    load_chunk(1, 1); cp_commit();
    load_chunk(2, 2); cp_commit();
    for (int i = 0; i < NC; i++) {
        cp_wait2();
        __syncthreads();
        int nx = i + NS16 - 1;
        if (nx < NC) load_chunk(nx, nx % NS16);
        cp_commit();
        L.compute(i % NS16, acc);
    }

    __syncthreads();
    float* eps = (float*)smraw;
    int lr = L.lane >> 2, lc = L.lane & 3;
    if (L.wn == 1) {
        #pragma unroll
        for (int mi = 0; mi < 2; mi++)
            #pragma unroll
            for (int half = 0; half < 2; half++) {
                int ml = L.wm * 32 + mi * 16 + half * 8 + lr;
                #pragma unroll
                for (int ni = 0; ni < 8; ni++) {
                    eps[ml * 66 + ni * 8 + lc * 2 + 0] = acc[mi][ni][half * 2 + 0];
                    eps[ml * 66 + ni * 8 + lc * 2 + 1] = acc[mi][ni][half * 2 + 1];
                }
            }
    }
    __syncthreads();
    if (L.wn == 0) {
        unsigned short* hrow = g_hid16 + (size_t)e * NTOK * FF + c0;
        #pragma unroll
        for (int mi = 0; mi < 2; mi++)
            #pragma unroll
            for (int half = 0; half < 2; half++) {
                int ml = L.wm * 32 + mi * 16 + half * 8 + lr;
                int m = m0 + ml;
                if (m < cnt) {
                    #pragma unroll
                    for (int ni = 0; ni < 8; ni++) {
                        float x0 = acc[mi][ni][half * 2 + 0];
                        float x1 = acc[mi][ni][half * 2 + 1];
                        float a3x = eps[ml * 66 + ni * 8 + lc * 2 + 0];
                        float a3y = eps[ml * 66 + ni * 8 + lc * 2 + 1];
                        float v0 = x0 / (1.f + __expf(-x0)) * a3x;
                        float v1 = x1 / (1.f + __expf(-x1)) * a3y;
                        __nv_bfloat162 o(__float2bfloat16_rn(v0), __float2bfloat16_rn(v1));
                        *(__nv_bfloat162*)(hrow + (size_t)m * FF + ni * 8 + lc * 2) = o;
                    }
                }
            }
    }
}

// ---- MoE pass 3:  m-block = blockIdx.x (fastest) ----
__global__ __launch_bounds__(256, 2)
void moe2_gemm()
{
    int e = blockIdx.z;
    int cnt = g_counts[e];
    int m0 = blockIdx.x * 128;
    if (m0 >= cnt) return;
    int n0 = blockIdx.y * 128;

    extern __shared__ char smraw[];
    int tid = threadIdx.x;
    uint32_t sbase = smem_u32(smraw);
    Bf16Loop L; L.init(sbase, tid);

    int row = tid >> 1, sl = (tid & 1) * 2;
    const unsigned short* arow = g_hid16 + (size_t)e * NTOK * FF + (size_t)(m0 + row) * FF;
    const unsigned short* brow = g_w2t + (size_t)e * FF * CC + (size_t)(n0 + row) * FF;

    uint32_t aD[NS16], bD[NS16];
    #pragma unroll
    for (int s = 0; s < NS16; s++) {
        aD[s] = sbase + s * (2 * HTILE_B) + row * HROW + sl * 16;
        bD[s] = aD[s] + HTILE_B;
    }
    auto load_chunk = [&](int ci, int p) {
        const unsigned short* as = arow + ci * 32 + sl * 8;
        cp16(aD[p], as); cp16(aD[p] + 16, as + 8);
        const unsigned short* bs = brow + ci * 32 + sl * 8;
        cp16(bD[p], bs); cp16(bD[p] + 16, bs + 8);
    };

    float acc[2][8][4];
    #pragma unroll
    for (int mi = 0; mi < 2; mi++)
        #pragma unroll
        for (int ni = 0; ni < 8; ni++)
            #pragma unroll
            for (int q = 0; q < 4; q++) acc[mi][ni][q] = 0.f;

    const int NC = FF / 32;
    load_chunk(0, 0); cp_commit();
    load_chunk(1, 1); cp_commit();
    load_chunk(2, 2); cp_commit();
    for (int i = 0; i < NC; i++) {
        cp_wait2();
        __syncthreads();
        int nx = i + NS16 - 1;
        if (nx < NC) load_chunk(nx, nx % NS16);
        cp_commit();
        L.compute(i % NS16, acc);
    }

    int lr = L.lane >> 2, lc = L.lane & 3;
    float* Co = g_moe + (size_t)e * NTOK * CC;
    #pragma unroll
    for (int mi = 0; mi < 2; mi++)
        #pragma unroll
        for (int half = 0; half < 2; half++) {
            int m = m0 + L.wm * 32 + mi * 16 + half * 8 + lr;
            if (m < cnt) {
                #pragma unroll
                for (int ni = 0; ni < 8; ni++) {
                    float2 v;
                    v.x = acc[mi][ni][half * 2 + 0];
                    v.y = acc[mi][ni][half * 2 + 1];
                    *(float2*)(Co + (size_t)m * CC + n0 + L.wn * 64 + ni * 8 + lc * 2) = v;
                }
            }
        }
}

// ---------------- weight transpose+convert (+ zero counts) ----------------
__global__ void transpose_all(const float* __restrict__ w1, const float* __restrict__ w3,
                              const float* __restrict__ w2) {
    if (blockIdx.x == 0 && blockIdx.z == 0 && threadIdx.x < EE)
        g_counts[threadIdx.x] = 0;
    __shared__ float t[32][33];
    int z = blockIdx.z;
    const float* src; unsigned short* dst; int K, N;
    if (z < 8)       { src = w1 + (size_t)z * CC * FF;        dst = g_w1t + (size_t)z * CC * FF;        K = CC; N = FF; }
    else if (z < 16) { src = w3 + (size_t)(z - 8) * CC * FF;  dst = g_w3t + (size_t)(z - 8) * CC * FF;  K = CC; N = FF; }
    else             { src = w2 + (size_t)(z - 16) * FF * CC; dst = g_w2t + (size_t)(z - 16) * FF * CC; K = FF; N = CC; }
    int nb = N / 32;
    int n0 = (blockIdx.x % nb) * 32;
    int k0 = (blockIdx.x / nb) * 32;
    int tx = threadIdx.x & 31, ty = threadIdx.x >> 5;
    #pragma unroll
    for (int p = 0; p < 4; p++)
        t[ty + p * 8][tx] = src[(size_t)(k0 + ty + p * 8) * N + n0 + tx];
    __syncthreads();
    #pragma unroll
    for (int p = 0; p < 4; p++) {
        __nv_bfloat16 v = __float2bfloat16_rn(t[tx][ty + p * 8]);
        dst[(size_t)(n0 + ty + p * 8) * K + k0 + tx] = *(unsigned short*)&v;
    }
}

// ---------------- rmsnorm (+ optional fused MoE routing) ----------------
__global__ void rmsnorm_kernel(const float* __restrict__ x,
                               const float* __restrict__ w,
                               float* __restrict__ o,
                               unsigned short* __restrict__ o16,
                               const float* __restrict__ gw) {
    int row = blockIdx.x;
    const float* xr = x + (size_t)row * CC;
    __shared__ float red[8];
    __shared__ float gred[8][EE];
    float s = 0.f;
    for (int c = threadIdx.x; c < CC; c += 256) { float v = xr[c]; s += v * v; }
    #pragma unroll
    for (int off = 16; off; off >>= 1) s += __shfl_xor_sync(~0u, s, off);
    if ((threadIdx.x & 31) == 0) red[threadIdx.x >> 5] = s;
    __syncthreads();
    if (threadIdx.x < 8) {
        float t = red[threadIdx.x];
        #pragma unroll
        for (int off = 4; off; off >>= 1) t += __shfl_xor_sync(0xff, t, off);
        if (threadIdx.x == 0) red[0] = t;
    }
    __syncthreads();
    float inv = rsqrtf(red[0] * (1.0f / CC) + EPS);
    float la[EE];
    #pragma unroll
    for (int e = 0; e < EE; e++) la[e] = 0.f;
    for (int c = threadIdx.x; c < CC; c += 256) {
        float v = xr[c] * inv * w[c];
        if (o) o[(size_t)row * CC + c] = v;
        if (o16) {
            __nv_bfloat16 h = __float2bfloat16_rn(v);
            o16[(size_t)row * CC + c] = *(unsigned short*)&h;
        }
        if (gw) {
            #pragma unroll
            for (int e = 0; e < EE; e++) la[e] += v * gw[c * EE + e];
        }
    }
    if (gw) {
        #pragma unroll
        for (int e = 0; e < EE; e++)
            #pragma unroll
            for (int off = 16; off; off >>= 1)
                la[e] += __shfl_xor_sync(~0u, la[e], off);
        if ((threadIdx.x & 31) == 0) {
            #pragma unroll
            for (int e = 0; e < EE; e++) gred[threadIdx.x >> 5][e] = la[e];
        }
        __syncthreads();
        if (threadIdx.x == 0) {
            float acc[EE];
            #pragma unroll
            for (int e = 0; e < EE; e++) {
                float t = 0.f;
                #pragma unroll
                for (int wq2 = 0; wq2 < 8; wq2++) t += gred[wq2][e];
                acc[e] = t;
            }
            int i0 = 0;
            #pragma unroll
            for (int e = 1; e < EE; e++) if (acc[e] > acc[i0]) i0 = e;
            int i1 = -1;
            #pragma unroll
            for (int e = 0; e < EE; e++)
                if (e != i0 && (i1 < 0 || acc[e] > acc[i1])) i1 = e;
            float p1 = __expf(acc[i1] - acc[i0]);
            float sw = 1.0f + p1;
            float w0 = 1.0f / sw, w1 = p1 / sw;
            int pos0 = atomicAdd(&g_counts[i0], 1);
            int pos1 = atomicAdd(&g_counts[i1], 1);
            g_tok[i0 * NTOK + pos0] = row;
            g_tok[i1 * NTOK + pos1] = row;
            g_tidx[row * 2 + 0] = i0; g_tidx[row * 2 + 1] = i1;
            g_tpos[row * 2 + 0] = pos0; g_tpos[row * 2 + 1] = pos1;
            g_twt [row * 2 + 0] = w0;  g_twt [row * 2 + 1] = w1;
        }
    }
}

__global__ void rope_all_kernel(float* __restrict__ q, float* __restrict__ k) {
    int idx = blockIdx.x * blockDim.x + threadIdx.x;
    const int qtot = NTOK * NH * 32;
    const int ktot = NTOK * NKV * 32;
    float* t; int nh;
    if (idx < qtot) { t = q; nh = NH; }
    else { idx -= qtot; if (idx >= ktot) return; t = k; nh = NKV; }
    int n = idx / (nh * 32);
    int r = idx - n * (nh * 32);
    int h = r >> 5;
    int d = r & 31;
    int pos = n & (TT - 1);
    float* p = t + ((size_t)n * nh + h) * HD;
    float fr  = __powf(10000.0f, -(float)d * (1.0f / 32.0f));
    float ang = (float)pos * fr;
    float cs = cosf(ang), sn = sinf(ang);
    float x1 = p[d], x2 = p[d + 32];
    p[d]      = x1 * cs - x2 * sn;
    p[d + 32] = x2 * cs + x1 * sn;
}

// ---------------- tensor-core flash attention (tf32) ----------------
#define TSTR 40

__global__ __launch_bounds__(128, 2)
void attn_mma(const float* __restrict__ q, const float* __restrict__ k,
              const float* __restrict__ v, float* __restrict__ out)
{
    __shared__ float Kt[64 * TSTR];          // [d][j]
    __shared__ float Vt[64 * TSTR];          // [d][j]
    __shared__ uint32_t Psm[4][32 * TSTR];   // per-warp P (tf32 bits)

    int bh = blockIdx.y;
    int b = bh >> 4, h = bh & 15;
    int kh = h >> 2;
    int q0 = blockIdx.x * 128;
    int tid = threadIdx.x;
    int warp = tid >> 5, lane = tid & 31;
    int lr = lane >> 2, lc = lane & 3;
    int qw = q0 + warp * 32;

    uint32_t Qf[2][8][4];
    #pragma unroll
    for (int mi = 0; mi < 2; mi++) {
        const float* qp0 = q + ((size_t)(b * TT + qw + mi * 16 + lr) * NH + h) * HD;
        const float* qp1 = qp0 + (size_t)8 * NH * HD;
        #pragma unroll
        for (int kk = 0; kk < 8; kk++) {
            Qf[mi][kk][0] = f2tf(qp0[kk * 8 + lc] * 0.125f);
            Qf[mi][kk][1] = f2tf(qp1[kk * 8 + lc] * 0.125f);
            Qf[mi][kk][2] = f2tf(qp0[kk * 8 + lc + 4] * 0.125f);
            Qf[mi][kk][3] = f2tf(qp1[kk * 8 + lc + 4] * 0.125f);
        }
    }

    float O[2][8][4];
    #pragma unroll
    for (int mi = 0; mi < 2; mi++)
        #pragma unroll
        for (int ni = 0; ni < 8; ni++)
            #pragma unroll
            for (int c = 0; c < 4; c++) O[mi][ni][c] = 0.f;
    float mrow[2][2] = { {-1e30f, -1e30f}, {-1e30f, -1e30f} };
    float lrow[2][2] = { {0.f, 0.f}, {0.f, 0.f} };

    int kmin = q0 - WIN + 1; if (kmin < 0) kmin = 0;
    kmin &= ~31;
    int kmax = q0 + 127;

    int cj = tid & 31, dg = tid >> 5;
    const float* kr0 = k + ((size_t)(b * TT + cj) * NKV + kh) * HD + dg * 16;
    const float* vr0 = v + ((size_t)(b * TT + cj) * NKV + kh) * HD + dg * 16;

    for (int kt = kmin; kt <= kmax; kt += 32) {
        __syncthreads();
        {
            const float* krp = kr0 + (size_t)kt * NKV * HD;
            const float* vrp = vr0 + (size_t)kt * NKV * HD;
            #pragma unroll
            for (int u = 0; u < 4; u++) {
                float4 kv = *(const float4*)(krp + u * 4);
                float4 vv = *(const float4*)(vrp + u * 4);
                int d0 = dg * 16 + u * 4;
                Kt[(d0 + 0) * TSTR + cj] = kv.x; Kt[(d0 + 1) * TSTR + cj] = kv.y;
                Kt[(d0 + 2) * TSTR + cj] = kv.z; Kt[(d0 + 3) * TSTR + cj] = kv.w;
                Vt[(d0 + 0) * TSTR + cj] = vv.x; Vt[(d0 + 1) * TSTR + cj] = vv.y;
                Vt[(d0 + 2) * TSTR + cj] = vv.z; Vt[(d0 + 3) * TSTR + cj] = vv.w;
            }
        }
        __syncthreads();

        float S[2][4][4];
        #pragma unroll
        for (int mi = 0; mi < 2; mi++)
            #pragma unroll
            for (int nj = 0; nj < 4; nj++)
                #pragma unroll
                for (int c = 0; c < 4; c++) S[mi][nj][c] = 0.f;
        #pragma unroll
        for (int kk = 0; kk < 8; kk++) {
            uint32_t bf[4][2];
            #pragma unroll
            for (int nj = 0; nj < 4; nj++) {
                bf[nj][0] = f2tf(Kt[(kk * 8 + lc) * TSTR + nj * 8 + lr]);
                bf[nj][1] = f2tf(Kt[(kk * 8 + lc + 4) * TSTR + nj * 8 + lr]);
            }
            #pragma unroll
            for (int mi = 0; mi < 2; mi++)
                #pragma unroll
                for (int nj = 0; nj < 4; nj++)
                    mma8(S[mi][nj], Qf[mi][kk], bf[nj]);
        }

        #pragma unroll
        for (int mi = 0; mi < 2; mi++) {
            #pragma unroll
            for (int h2 = 0; h2 < 2; h2++) {
                int qi = qw + mi * 16 + h2 * 8 + lr;
                float tm = -1e30f;
                #pragma unroll
                for (int nj = 0; nj < 4; nj++) {
                    #pragma unroll
                    for (int c = 0; c < 2; c++) {
                        int j = kt + nj * 8 + lc * 2 + c;
                        bool ok = (j <= qi) && (j > qi - WIN);
                        float sv = ok ? S[mi][nj][h2 * 2 + c] : -1e30f;
                        S[mi][nj][h2 * 2 + c] = sv;
                        tm = fmaxf(tm, sv);
                    }
                }
                tm = fmaxf(tm, __shfl_xor_sync(~0u, tm, 1));
                tm = fmaxf(tm, __shfl_xor_sync(~0u, tm, 2));
                float mn = fmaxf(mrow[mi][h2], tm);
                float corr = __expf(mrow[mi][h2] - mn);
                #pragma unroll
                for (int ni = 0; ni < 8; ni++) {
                    O[mi][ni][h2 * 2 + 0] *= corr;
                    O[mi][ni][h2 * 2 + 1] *= corr;
                }
                float ls = 0.f;
                #pragma unroll
                for (int nj = 0; nj < 4; nj++) {
                    uint2 pp;
                    float sv0 = S[mi][nj][h2 * 2 + 0];
                    float sv1 = S[mi][nj][h2 * 2 + 1];
                    float p0 = (sv0 > -9e29f) ? __expf(sv0 - mn) : 0.f;
                    float p1 = (sv1 > -9e29f) ? __expf(sv1 - mn) : 0.f;
                    ls += p0 + p1;
                    pp.x = f2tf(p0); pp.y = f2tf(p1);
                    *(uint2*)&Psm[warp][(mi * 16 + h2 * 8 + lr) * TSTR + nj * 8 + lc * 2] = pp;
                }
                ls += __shfl_xor_sync(~0u, ls, 1);
                ls += __shfl_xor_sync(~0u, ls, 2);
                lrow[mi][h2] = lrow[mi][h2] * corr + ls;
                mrow[mi][h2] = mn;
            }
        }
        __syncwarp();

        #pragma unroll
        for (int kk = 0; kk < 4; kk++) {
            uint32_t a[2][4], bf[8][2];
            #pragma unroll
            for (int mi = 0; mi < 2; mi++) {
                const uint32_t* ap = &Psm[warp][(mi * 16 + lr) * TSTR + kk * 8 + lc];
                a[mi][0] = ap[0];
                a[mi][1] = ap[8 * TSTR];
                a[mi][2] = ap[4];
                a[mi][3] = ap[8 * TSTR + 4];
            }
            #pragma unroll
            for (int ni = 0; ni < 8; ni++) {
                bf[ni][0] = f2tf(Vt[(ni * 8 + lr) * TSTR + kk * 8 + lc]);
                bf[ni][1] = f2tf(Vt[(ni * 8 + lr) * TSTR + kk * 8 + lc + 4]);
            }
            #pragma unroll
            for (int mi = 0; mi < 2; mi++)
                #pragma unroll
                for (int ni = 0; ni < 8; ni++)
                    mma8(O[mi][ni], a[mi], bf[ni]);
        }
    }

    #pragma unroll
    for (int mi = 0; mi < 2; mi++) {
        #pragma unroll
        for (int h2 = 0; h2 < 2; h2++) {
            int qi = qw + mi * 16 + h2 * 8 + lr;
            float inv = 1.f / lrow[mi][h2];
            float* orow = out + ((size_t)(b * TT + qi) * NH + h) * HD;
            #pragma unroll
            for (int ni = 0; ni < 8; ni++) {
                float2 vv;
                vv.x = O[mi][ni][h2 * 2 + 0] * inv;
                vv.y = O[mi][ni][h2 * 2 + 1] * inv;
                *(float2*)(orow + ni * 8 + lc * 2) = vv;
            }
        }
    }
}

// ---------------- final combine ----------------
__global__ void combine_kernel(float* __restrict__ out) {
    int idx = blockIdx.x * blockDim.x + threadIdx.x;
    int n  = idx >> 8;
    int c4 = idx & 255;
    int e0 = g_tidx[n * 2], e1 = g_tidx[n * 2 + 1];
    int p0 = g_tpos[n * 2], p1 = g_tpos[n * 2 + 1];
    float w0 = g_twt[n * 2], w1 = g_twt[n * 2 + 1];
    float4 h4 = ((const float4*)g_hres)[idx];
    float4 a = ((const float4*)(g_moe + ((size_t)e0 * NTOK + p0) * CC))[c4];
    float4 b = ((const float4*)(g_moe + ((size_t)e1 * NTOK + p1) * CC))[c4];
    float4 o;
    o.x = h4.x + w0 * a.x + w1 * b.x;
    o.y = h4.y + w0 * a.y + w1 * b.y;
    o.z = h4.z + w0 * a.z + w1 * b.z;
    o.w = h4.w + w0 * a.w + w1 * b.w;
    ((float4*)out)[idx] = o;
}

// ---------------- launch ----------------
extern "C" void kernel_launch(void* const* d_in, const int* in_sizes, int n_in,
                              void* d_out, int out_size) {
    const float* x           = (const float*)d_in[0];
    const float* attn_norm_w = (const float*)d_in[1];
    const float* ffn_norm_w  = (const float*)d_in[2];
    const float* wq          = (const float*)d_in[3];
    const float* wk          = (const float*)d_in[4];
    const float* wv          = (const float*)d_in[5];
    const float* wo          = (const float*)d_in[6];
    const float* gate_w      = (const float*)d_in[7];
    const float* w1          = (const float*)d_in[8];
    const float* w2          = (const float*)d_in[9];
    const float* w3          = (const float*)d_in[10];
    float* out = (float*)d_out;

    cudaFuncSetAttribute(qkv_gemm,    cudaFuncAttributeMaxDynamicSharedMemorySize, SMEMG);
    cudaFuncSetAttribute(wo_gemm,     cudaFuncAttributeMaxDynamicSharedMemorySize, SMEMG);
    cudaFuncSetAttribute(moe13_fused, cudaFuncAttributeMaxDynamicSharedMemorySize, SMEM16);
    cudaFuncSetAttribute(moe2_gemm,   cudaFuncAttributeMaxDynamicSharedMemorySize, SMEM16);

    float *hn, *qb, *kb, *vb, *att, *hres, *gbuf;
    unsigned short *gb16;
    cudaGetSymbolAddress((void**)&hn,    g_hn);
    cudaGetSymbolAddress((void**)&qb,    g_q);
    cudaGetSymbolAddress((void**)&kb,    g_k);
    cudaGetSymbolAddress((void**)&vb,    g_v);
    cudaGetSymbolAddress((void**)&att,   g_att);
    cudaGetSymbolAddress((void**)&hres,  g_hres);
    cudaGetSymbolAddress((void**)&gbuf,  g_gbuf);
    cudaGetSymbolAddress((void**)&gb16,  g_gb16);

    // 1: weight transpose+convert (+ zero counts)
    transpose_all<<<dim3(4096, 1, 24), 256>>>(w1, w3, w2);
    // 2: attn rmsnorm
    rmsnorm_kernel<<<NTOK, 256>>>(x, attn_norm_w, hn, nullptr, nullptr);
    // 3: fused QKV projections
    qkv_gemm<<<dim3(12, 32), 256, SMEMG>>>(hn, wq, wk, wv);
    // 4: RoPE
    {
        int tot = NTOK * (NH + NKV) * 32;
        rope_all_kernel<<<(tot + 255) / 256, 256>>>(qb, kb);
    }
    // 5: tensor-core sliding-window attention
    attn_mma<<<dim3(TT / 128, BB * NH), 128>>>(qb, kb, vb, att);
    // 6: output projection + residual
    wo_gemm<<<dim3(8, 32), 256, SMEMG>>>(att, wo, hres, x);
    // 7: ffn rmsnorm + fused routing
    rmsnorm_kernel<<<NTOK, 256>>>(hres, ffn_norm_w, gbuf, gb16, gate_w);
    // 8: fused MoE pass 1+2  (m fastest for L2 weight reuse)
    moe13_fused<<<dim3(NTOK / 128, FF / 64, EE), 256, SMEM16>>>();
    // 9: MoE pass 3
    moe2_gemm<<<dim3(NTOK / 128, CC / 128, EE), 256, SMEM16>>>();
    // 10: final combine + residual
    combine_kernel<<<(NTOK * CC / 4) / 256, 256>>>(out);
}

// round 12
// speedup vs baseline: 1.4037x; 1.4037x over previous
#include <cuda_runtime.h>
#include <cuda_bf16.h>
#include <cstdint>

// ---------------- problem constants ----------------
#define BB   4
#define TT   1024
#define CC   1024
#define NH   16
#define NKV  4
#define HD   64
#define EE   8
#define FF   4096
#define WIN  256
#define NTOK (BB*TT)          // 4096
#define EPS  1e-6f

// ---------------- scratch ----------------
__device__ float g_hn  [(size_t)NTOK*CC];
__device__ float g_q   [(size_t)NTOK*NH*HD];
__device__ float g_k   [(size_t)NTOK*NKV*HD];
__device__ float g_v   [(size_t)NTOK*NKV*HD];
__device__ float g_att [(size_t)NTOK*CC];
__device__ float g_hres[(size_t)NTOK*CC];
__device__ int   g_counts[EE];
__device__ int   g_tok [(size_t)EE*NTOK];
__device__ int   g_tidx[(size_t)NTOK*2];
__device__ int   g_tpos[(size_t)NTOK*2];
__device__ float g_twt [(size_t)NTOK*2];
__device__ float g_moe [(size_t)EE*NTOK*CC];
__device__ unsigned short g_gb16 [(size_t)NTOK*CC];
__device__ unsigned short g_hid16[(size_t)EE*NTOK*FF];
__device__ unsigned short g_w1t  [(size_t)EE*CC*FF];    // [e][FF][CC] bf16
__device__ unsigned short g_w3t  [(size_t)EE*CC*FF];
__device__ unsigned short g_w2t  [(size_t)EE*FF*CC];    // [e][CC][FF] bf16

// ---------------- helpers ----------------
__device__ __forceinline__ uint32_t smem_u32(const void* p) {
    uint32_t a;
    asm("{ .reg .u64 t; cvta.to.shared.u64 t, %1; cvt.u32.u64 %0, t; }" : "=r"(a) : "l"(p));
    return a;
}
__device__ __forceinline__ void cp16(uint32_t dst, const void* src) {
    asm volatile("cp.async.cg.shared.global [%0], [%1], 16;" :: "r"(dst), "l"(src));
}
__device__ __forceinline__ void cp_commit() { asm volatile("cp.async.commit_group;" ::: "memory"); }
__device__ __forceinline__ void cp_wait1() { asm volatile("cp.async.wait_group 1;" ::: "memory"); }
__device__ __forceinline__ void cp_wait2() { asm volatile("cp.async.wait_group 2;" ::: "memory"); }
__device__ __forceinline__ uint32_t f2tf(float f) {
    uint32_t r; asm("cvt.rna.tf32.f32 %0, %1;" : "=r"(r) : "f"(f)); return r;
}
__device__ __forceinline__ void mma8(float* c, const uint32_t* a, const uint32_t* b) {
    asm volatile("mma.sync.aligned.m16n8k8.row.col.f32.tf32.tf32.f32 "
                 "{%0,%1,%2,%3}, {%4,%5,%6,%7}, {%8,%9}, {%0,%1,%2,%3};"
                 : "+f"(c[0]), "+f"(c[1]), "+f"(c[2]), "+f"(c[3])
                 : "r"(a[0]), "r"(a[1]), "r"(a[2]), "r"(a[3]), "r"(b[0]), "r"(b[1]));
}
__device__ __forceinline__ void mma16(float* c, const uint32_t* a, const uint32_t* b) {
    asm volatile("mma.sync.aligned.m16n8k16.row.col.f32.bf16.bf16.f32 "
                 "{%0,%1,%2,%3}, {%4,%5,%6,%7}, {%8,%9}, {%0,%1,%2,%3};"
                 : "+f"(c[0]), "+f"(c[1]), "+f"(c[2]), "+f"(c[3])
                 : "r"(a[0]), "r"(a[1]), "r"(a[2]), "r"(a[3]), "r"(b[0]), "r"(b[1]));
}
__device__ __forceinline__ void ldsm4(uint32_t* r, uint32_t addr) {
    asm volatile("ldmatrix.sync.aligned.m8n8.x4.shared.b16 {%0,%1,%2,%3}, [%4];"
                 : "=r"(r[0]), "=r"(r[1]), "=r"(r[2]), "=r"(r[3]) : "r"(addr));
}

// ================= tf32 GEMM core (attention path) =================
#define NSTG 3
#define ASTRIDE 36
#define BSTRIDE 136
#define ASZ (128*ASTRIDE)
#define BSZ (32*BSTRIDE)
#define SMEMG (NSTG*(ASZ+BSZ)*4)   // 107520 bytes

__device__ __forceinline__ void gemm_body_tf32(
    const float* __restrict__ A, int m0,
    const float* __restrict__ W, float* __restrict__ C, const float* __restrict__ res,
    int K, int Nw, int nloc, float* smf)
{
    float* Abuf[NSTG];
    float* Bbuf[NSTG];
    #pragma unroll
    for (int s = 0; s < NSTG; s++) {
        Abuf[s] = smf + s * ASZ;
        Bbuf[s] = smf + NSTG * ASZ + s * BSZ;
    }
    int tid = threadIdx.x;
    int lane = tid & 31, warp = tid >> 5;
    int wm = warp & 3, wn = warp >> 2;

    int ar = tid >> 1;
    int af = (tid & 1) * 4;
    const float* arow = A + (size_t)(m0 + ar) * K;
    int bk = tid >> 3;
    int bf = tid & 7;
    const float* brow = W + (size_t)bk * Nw + nloc + bf * 4;

    uint32_t aD[NSTG], bD[NSTG];
    #pragma unroll
    for (int p = 0; p < NSTG; p++) {
        aD[p] = smem_u32(Abuf[p]) + (ar * ASTRIDE + af * 4) * 4;
        bD[p] = smem_u32(Bbuf[p]) + (bk * BSTRIDE + bf * 4) * 4;
    }

    auto load_chunk = [&](int ci, int p) {
        const float* as = arow + ci * 32 + af * 4;
        #pragma unroll
        for (int j = 0; j < 4; j++) cp16(aD[p] + j * 16, as + j * 4);
        const float* bs = brow + (size_t)ci * 32 * Nw;
        #pragma unroll
        for (int j = 0; j < 4; j++) cp16(bD[p] + j * 128, bs + j * 32);
    };

    float acc[2][8][4];
    #pragma unroll
    for (int mi = 0; mi < 2; mi++)
        #pragma unroll
        for (int ni = 0; ni < 8; ni++)
            #pragma unroll
            for (int q = 0; q < 4; q++) acc[mi][ni][q] = 0.f;

    int lr = lane >> 2, lc = lane & 3;

    auto compute = [&](int p) {
        const float* Am = Abuf[p];
        const float* Bm = Bbuf[p];
        #pragma unroll
        for (int kk = 0; kk < 4; kk++) {
            int kb = kk * 8;
            uint32_t a[2][4], b[8][2];
            #pragma unroll
            for (int mi = 0; mi < 2; mi++) {
                const float* ap = Am + (wm * 32 + mi * 16 + lr) * ASTRIDE + kb + lc;
                a[mi][0] = f2tf(ap[0]);
                a[mi][1] = f2tf(ap[8 * ASTRIDE]);
                a[mi][2] = f2tf(ap[4]);
                a[mi][3] = f2tf(ap[8 * ASTRIDE + 4]);
            }
            #pragma unroll
            for (int ni = 0; ni < 8; ni++) {
                const float* bp = Bm + (kb + lc) * BSTRIDE + wn * 64 + ni * 8 + lr;
                b[ni][0] = f2tf(bp[0]);
                b[ni][1] = f2tf(bp[4 * BSTRIDE]);
            }
            #pragma unroll
            for (int mi = 0; mi < 2; mi++)
                #pragma unroll
                for (int ni = 0; ni < 8; ni++)
                    mma8(acc[mi][ni], a[mi], b[ni]);
        }
    };

    int NC = K / 32;
    load_chunk(0, 0); cp_commit();
    load_chunk(1, 1); cp_commit();
    for (int i = 0; i < NC; i++) {
        cp_wait1();
        __syncthreads();
        int nx = i + NSTG - 1;
        if (nx < NC) load_chunk(nx, nx % NSTG);
        cp_commit();
        compute(i % NSTG);
    }

    int tc = (lane & 3) * 2;
    #pragma unroll
    for (int mi = 0; mi < 2; mi++) {
        #pragma unroll
        for (int half = 0; half < 2; half++) {
            int m = m0 + wm * 32 + mi * 16 + half * 8 + lr;
            float* crow = C + (size_t)m * Nw + nloc + wn * 64;
            #pragma unroll
            for (int ni = 0; ni < 8; ni++) {
                float c0 = acc[mi][ni][half * 2 + 0];
                float c1 = acc[mi][ni][half * 2 + 1];
                if (res) {
                    const float2 rr = *(const float2*)(res + (size_t)m * Nw + nloc + wn * 64 + ni * 8 + tc);
                    c0 += rr.x; c1 += rr.y;
                }
                float2 v; v.x = c0; v.y = c1;
                *(float2*)(crow + ni * 8 + tc) = v;
            }
        }
    }
}

__global__ __launch_bounds__(256, 2)
void wo_gemm(const float* __restrict__ A, const float* __restrict__ W,
             float* __restrict__ C, const float* __restrict__ res)
{
    extern __shared__ float smf[];
    gemm_body_tf32(A, blockIdx.y * 128, W, C, res, CC, CC, blockIdx.x * 128, smf);
}

__global__ __launch_bounds__(256, 2)
void qkv_gemm(const float* __restrict__ hn,
              const float* __restrict__ wq, const float* __restrict__ wk,
              const float* __restrict__ wv)
{
    extern __shared__ float smf[];
    int m0 = blockIdx.y * 128;
    int nb = blockIdx.x;
    const float* W; float* O; int Nw, nloc;
    if (nb < 8)       { W = wq; O = g_q; Nw = NH * HD;  nloc = nb * 128; }
    else if (nb < 10) { W = wk; O = g_k; Nw = NKV * HD; nloc = (nb - 8) * 128; }
    else              { W = wv; O = g_v; Nw = NKV * HD; nloc = (nb - 10) * 128; }
    gemm_body_tf32(hn, m0, W, O, (const float*)0, CC, Nw, nloc, smf);
}

// ================= bf16 GEMM core (MoE path, ldmatrix) =================
#define HROW 80
#define HTILE_B (128*HROW)
#define NS16 4
#define SMEM16 (NS16*2*HTILE_B)    // 81920 bytes

struct Bf16Loop {
    uint32_t sbase;
    int lane, wm, wn;
    uint32_t aR, aK, bR, bK;
    __device__ __forceinline__ void init(uint32_t sb, int tid) {
        sbase = sb;
        lane = tid & 31;
        int warp = tid >> 5;
        wm = warp & 3; wn = warp >> 2;
        aR = (lane & 7) + ((lane >> 3) & 1) * 8;
        aK = ((lane >> 4) & 1) * 16;
        bR = (lane & 7) + ((lane >> 4) & 1) * 8;
        bK = ((lane >> 3) & 1) * 16;
    }
    __device__ __forceinline__ void compute(int p, float acc[2][8][4]) {
        uint32_t Am = sbase + p * (2 * HTILE_B);
        uint32_t Bm = Am + HTILE_B;
        #pragma unroll
        for (int kk = 0; kk < 2; kk++) {
            uint32_t a[2][4], b[4][4];
            #pragma unroll
            for (int mi = 0; mi < 2; mi++)
                ldsm4(a[mi], Am + (wm * 32 + mi * 16 + aR) * HROW + kk * 32 + aK);
            #pragma unroll
            for (int p2 = 0; p2 < 4; p2++)
                ldsm4(b[p2], Bm + (wn * 64 + p2 * 16 + bR) * HROW + kk * 32 + bK);
            #pragma unroll
            for (int mi = 0; mi < 2; mi++)
                #pragma unroll
                for (int ni = 0; ni < 8; ni++)
                    mma16(acc[mi][ni], a[mi], &b[ni >> 1][(ni & 1) * 2]);
        }
    }
};

// ---- fused MoE pass 1+2 (R9 grid order: n-block = blockIdx.x fastest) ----
__global__ __launch_bounds__(256, 2)
void moe13_fused()
{
    int e = blockIdx.z;
    int cnt = g_counts[e];
    int m0 = blockIdx.y * 128;
    if (m0 >= cnt) return;
    int c0 = blockIdx.x * 64;

    extern __shared__ char smraw[];
    int tid = threadIdx.x;
    uint32_t sbase = smem_u32(smraw);
    Bf16Loop L; L.init(sbase, tid);

    int row = tid >> 1, sl = (tid & 1) * 2;
    const unsigned short* arow;
    {
        int grow = m0 + row;
        int g2 = (grow < cnt) ? grow : 0;
        arow = g_gb16 + (size_t)g_tok[e * NTOK + g2] * CC;
    }
    const unsigned short* brow = (row < 64)
        ? g_w1t + (size_t)e * CC * FF + (size_t)(c0 + row) * CC
        : g_w3t + (size_t)e * CC * FF + (size_t)(c0 + row - 64) * CC;

    uint32_t aD[NS16], bD[NS16];
    #pragma unroll
    for (int s = 0; s < NS16; s++) {
        aD[s] = sbase + s * (2 * HTILE_B) + row * HROW + sl * 16;
        bD[s] = aD[s] + HTILE_B;
    }
    auto load_chunk = [&](int ci, int p) {
        const unsigned short* as = arow + ci * 32 + sl * 8;
        cp16(aD[p], as); cp16(aD[p] + 16, as + 8);
        const unsigned short* bs = brow + ci * 32 + sl * 8;
        cp16(bD[p], bs); cp16(bD[p] + 16, bs + 8);
    };

    float acc[2][8][4];
    #pragma unroll
    for (int mi = 0; mi < 2; mi++)
        #pragma unroll
        for (int ni = 0; ni < 8; ni++)
            #pragma unroll
            for (int q = 0; q < 4; q++) acc[mi][ni][q] = 0.f;

    const int NC = CC / 32;
    load_chunk(0, 0); cp_commit();
    load_chunk(1, 1); cp_commit();
    load_chunk(2, 2); cp_commit();
    for (int i = 0; i < NC; i++) {
        cp_wait2();
        __syncthreads();
        int nx = i + NS16 - 1;
        if (nx < NC) load_chunk(nx, nx % NS16);
        cp_commit();
        L.compute(i % NS16, acc);
    }

    __syncthreads();
    float* eps = (float*)smraw;
    int lr = L.lane >> 2, lc = L.lane & 3;
    if (L.wn == 1) {
        #pragma unroll
        for (int mi = 0; mi < 2; mi++)
            #pragma unroll
            for (int half = 0; half < 2; half++) {
                int ml = L.wm * 32 + mi * 16 + half * 8 + lr;
                #pragma unroll
                for (int ni = 0; ni < 8; ni++) {
                    eps[ml * 66 + ni * 8 + lc * 2 + 0] = acc[mi][ni][half * 2 + 0];
                    eps[ml * 66 + ni * 8 + lc * 2 + 1] = acc[mi][ni][half * 2 + 1];
                }
            }
    }
    __syncthreads();
    if (L.wn == 0) {
        unsigned short* hrow = g_hid16 + (size_t)e * NTOK * FF + c0;
        #pragma unroll
        for (int mi = 0; mi < 2; mi++)
            #pragma unroll
            for (int half = 0; half < 2; half++) {
                int ml = L.wm * 32 + mi * 16 + half * 8 + lr;
                int m = m0 + ml;
                if (m < cnt) {
                    #pragma unroll
                    for (int ni = 0; ni < 8; ni++) {
                        float x0 = acc[mi][ni][half * 2 + 0];
                        float x1 = acc[mi][ni][half * 2 + 1];
                        float a3x = eps[ml * 66 + ni * 8 + lc * 2 + 0];
                        float a3y = eps[ml * 66 + ni * 8 + lc * 2 + 1];
                        float v0 = x0 / (1.f + __expf(-x0)) * a3x;
                        float v1 = x1 / (1.f + __expf(-x1)) * a3y;
                        __nv_bfloat162 o(__float2bfloat16_rn(v0), __float2bfloat16_rn(v1));
                        *(__nv_bfloat162*)(hrow + (size_t)m * FF + ni * 8 + lc * 2) = o;
                    }
                }
            }
    }
}

// ---- MoE pass 3 (R9 grid order) ----
__global__ __launch_bounds__(256, 2)
void moe2_gemm()
{
    int e = blockIdx.z;
    int cnt = g_counts[e];
    int m0 = blockIdx.y * 128;
    if (m0 >= cnt) return;
    int n0 = blockIdx.x * 128;

    extern __shared__ char smraw[];
    int tid = threadIdx.x;
    uint32_t sbase = smem_u32(smraw);
    Bf16Loop L; L.init(sbase, tid);

    int row = tid >> 1, sl = (tid & 1) * 2;
    const unsigned short* arow = g_hid16 + (size_t)e * NTOK * FF + (size_t)(m0 + row) * FF;
    const unsigned short* brow = g_w2t + (size_t)e * FF * CC + (size_t)(n0 + row) * FF;

    uint32_t aD[NS16], bD[NS16];
    #pragma unroll
    for (int s = 0; s < NS16; s++) {
        aD[s] = sbase + s * (2 * HTILE_B) + row * HROW + sl * 16;
        bD[s] = aD[s] + HTILE_B;
    }
    auto load_chunk = [&](int ci, int p) {
        const unsigned short* as = arow + ci * 32 + sl * 8;
        cp16(aD[p], as); cp16(aD[p] + 16, as + 8);
        const unsigned short* bs = brow + ci * 32 + sl * 8;
        cp16(bD[p], bs); cp16(bD[p] + 16, bs + 8);
    };

    float acc[2][8][4];
    #pragma unroll
    for (int mi = 0; mi < 2; mi++)
        #pragma unroll
        for (int ni = 0; ni < 8; ni++)
            #pragma unroll
            for (int q = 0; q < 4; q++) acc[mi][ni][q] = 0.f;

    const int NC = FF / 32;
    load_chunk(0, 0); cp_commit();
    load_chunk(1, 1); cp_commit();
    load_chunk(2, 2); cp_commit();
    for (int i = 0; i < NC; i++) {
        cp_wait2();
        __syncthreads();
        int nx = i + NS16 - 1;
        if (nx < NC) load_chunk(nx, nx % NS16);
        cp_commit();
        L.compute(i % NS16, acc);
    }

    int lr = L.lane >> 2, lc = L.lane & 3;
    float* Co = g_moe + (size_t)e * NTOK * CC;
    #pragma unroll
    for (int mi = 0; mi < 2; mi++)
        #pragma unroll
        for (int half = 0; half < 2; half++) {
            int m = m0 + L.wm * 32 + mi * 16 + half * 8 + lr;
            if (m < cnt) {
                #pragma unroll
                for (int ni = 0; ni < 8; ni++) {
                    float2 v;
                    v.x = acc[mi][ni][half * 2 + 0];
                    v.y = acc[mi][ni][half * 2 + 1];
                    *(float2*)(Co + (size_t)m * CC + n0 + L.wn * 64 + ni * 8 + lc * 2) = v;
                }
            }
        }
}

// ---------------- weight transpose+convert (+ zero counts) ----------------
__global__ void transpose_all(const float* __restrict__ w1, const float* __restrict__ w3,
                              const float* __restrict__ w2) {
    if (blockIdx.x == 0 && blockIdx.z == 0 && threadIdx.x < EE)
        g_counts[threadIdx.x] = 0;
    __shared__ float t[32][33];
    int z = blockIdx.z;
    const float* src; unsigned short* dst; int K, N;
    if (z < 8)       { src = w1 + (size_t)z * CC * FF;        dst = g_w1t + (size_t)z * CC * FF;        K = CC; N = FF; }
    else if (z < 16) { src = w3 + (size_t)(z - 8) * CC * FF;  dst = g_w3t + (size_t)(z - 8) * CC * FF;  K = CC; N = FF; }
    else             { src = w2 + (size_t)(z - 16) * FF * CC; dst = g_w2t + (size_t)(z - 16) * FF * CC; K = FF; N = CC; }
    int nb = N / 32;
    int n0 = (blockIdx.x % nb) * 32;
    int k0 = (blockIdx.x / nb) * 32;
    int tx = threadIdx.x & 31, ty = threadIdx.x >> 5;
    #pragma unroll
    for (int p = 0; p < 4; p++)
        t[ty + p * 8][tx] = src[(size_t)(k0 + ty + p * 8) * N + n0 + tx];
    __syncthreads();
    #pragma unroll
    for (int p = 0; p < 4; p++) {
        __nv_bfloat16 v = __float2bfloat16_rn(t[tx][ty + p * 8]);
        dst[(size_t)(n0 + ty + p * 8) * K + k0 + tx] = *(unsigned short*)&v;
    }
}

// ---------------- rmsnorm (+ optional fused MoE routing) ----------------
__global__ void rmsnorm_kernel(const float* __restrict__ x,
                               const float* __restrict__ w,
                               float* __restrict__ o,
                               unsigned short* __restrict__ o16,
                               const float* __restrict__ gw) {
    int row = blockIdx.x;
    const float* xr = x + (size_t)row * CC;
    __shared__ float red[8];
    __shared__ float gred[8][EE];
    float s = 0.f;
    for (int c = threadIdx.x; c < CC; c += 256) { float v = xr[c]; s += v * v; }
    #pragma unroll
    for (int off = 16; off; off >>= 1) s += __shfl_xor_sync(~0u, s, off);
    if ((threadIdx.x & 31) == 0) red[threadIdx.x >> 5] = s;
    __syncthreads();
    if (threadIdx.x < 8) {
        float t = red[threadIdx.x];
        #pragma unroll
        for (int off = 4; off; off >>= 1) t += __shfl_xor_sync(0xff, t, off);
        if (threadIdx.x == 0) red[0] = t;
    }
    __syncthreads();
    float inv = rsqrtf(red[0] * (1.0f / CC) + EPS);
    float la[EE];
    #pragma unroll
    for (int e = 0; e < EE; e++) la[e] = 0.f;
    for (int c = threadIdx.x; c < CC; c += 256) {
        float v = xr[c] * inv * w[c];
        if (o) o[(size_t)row * CC + c] = v;
        if (o16) {
            __nv_bfloat16 h = __float2bfloat16_rn(v);
            o16[(size_t)row * CC + c] = *(unsigned short*)&h;
        }
        if (gw) {
            #pragma unroll
            for (int e = 0; e < EE; e++) la[e] += v * gw[c * EE + e];
        }
    }
    if (gw) {
        #pragma unroll
        for (int e = 0; e < EE; e++)
            #pragma unroll
            for (int off = 16; off; off >>= 1)
                la[e] += __shfl_xor_sync(~0u, la[e], off);
        if ((threadIdx.x & 31) == 0) {
            #pragma unroll
            for (int e = 0; e < EE; e++) gred[threadIdx.x >> 5][e] = la[e];
        }
        __syncthreads();
        if (threadIdx.x == 0) {
            float acc[EE];
            #pragma unroll
            for (int e = 0; e < EE; e++) {
                float t = 0.f;
                #pragma unroll
                for (int wq2 = 0; wq2 < 8; wq2++) t += gred[wq2][e];
                acc[e] = t;
            }
            int i0 = 0;
            #pragma unroll
            for (int e = 1; e < EE; e++) if (acc[e] > acc[i0]) i0 = e;
            int i1 = -1;
            #pragma unroll
            for (int e = 0; e < EE; e++)
                if (e != i0 && (i1 < 0 || acc[e] > acc[i1])) i1 = e;
            float p1 = __expf(acc[i1] - acc[i0]);
            float sw = 1.0f + p1;
            float w0 = 1.0f / sw, w1 = p1 / sw;
            int pos0 = atomicAdd(&g_counts[i0], 1);
            int pos1 = atomicAdd(&g_counts[i1], 1);
            g_tok[i0 * NTOK + pos0] = row;
            g_tok[i1 * NTOK + pos1] = row;
            g_tidx[row * 2 + 0] = i0; g_tidx[row * 2 + 1] = i1;
            g_tpos[row * 2 + 0] = pos0; g_tpos[row * 2 + 1] = pos1;
            g_twt [row * 2 + 0] = w0;  g_twt [row * 2 + 1] = w1;
        }
    }
}

__global__ void rope_all_kernel(float* __restrict__ q, float* __restrict__ k) {
    int idx = blockIdx.x * blockDim.x + threadIdx.x;
    const int qtot = NTOK * NH * 32;
    const int ktot = NTOK * NKV * 32;
    float* t; int nh;
    if (idx < qtot) { t = q; nh = NH; }
    else { idx -= qtot; if (idx >= ktot) return; t = k; nh = NKV; }
    int n = idx / (nh * 32);
    int r = idx - n * (nh * 32);
    int h = r >> 5;
    int d = r & 31;
    int pos = n & (TT - 1);
    float* p = t + ((size_t)n * nh + h) * HD;
    float fr  = __powf(10000.0f, -(float)d * (1.0f / 32.0f));
    float ang = (float)pos * fr;
    float cs = cosf(ang), sn = sinf(ang);
    float x1 = p[d], x2 = p[d + 32];
    p[d]      = x1 * cs - x2 * sn;
    p[d + 32] = x2 * cs + x1 * sn;
}

// ---------------- tensor-core flash attention (tf32) ----------------
#define TSTR 40

__global__ __launch_bounds__(128, 2)
void attn_mma(const float* __restrict__ q, const float* __restrict__ k,
              const float* __restrict__ v, float* __restrict__ out)
{
    __shared__ float Kt[64 * TSTR];          // [d][j]
    __shared__ float Vt[64 * TSTR];          // [d][j]
    __shared__ uint32_t Psm[4][32 * TSTR];   // per-warp P (tf32 bits)

    int bh = blockIdx.y;
    int b = bh >> 4, h = bh & 15;
    int kh = h >> 2;
    int q0 = blockIdx.x * 128;
    int tid = threadIdx.x;
    int warp = tid >> 5, lane = tid & 31;
    int lr = lane >> 2, lc = lane & 3;
    int qw = q0 + warp * 32;

    uint32_t Qf[2][8][4];
    #pragma unroll
    for (int mi = 0; mi < 2; mi++) {
        const float* qp0 = q + ((size_t)(b * TT + qw + mi * 16 + lr) * NH + h) * HD;
        const float* qp1 = qp0 + (size_t)8 * NH * HD;
        #pragma unroll
        for (int kk = 0; kk < 8; kk++) {
            Qf[mi][kk][0] = f2tf(qp0[kk * 8 + lc] * 0.125f);
            Qf[mi][kk][1] = f2tf(qp1[kk * 8 + lc] * 0.125f);
            Qf[mi][kk][2] = f2tf(qp0[kk * 8 + lc + 4] * 0.125f);
            Qf[mi][kk][3] = f2tf(qp1[kk * 8 + lc + 4] * 0.125f);
        }
    }

    float O[2][8][4];
    #pragma unroll
    for (int mi = 0; mi < 2; mi++)
        #pragma unroll
        for (int ni = 0; ni < 8; ni++)
            #pragma unroll
            for (int c = 0; c < 4; c++) O[mi][ni][c] = 0.f;
    float mrow[2][2] = { {-1e30f, -1e30f}, {-1e30f, -1e30f} };
    float lrow[2][2] = { {0.f, 0.f}, {0.f, 0.f} };

    int kmin = q0 - WIN + 1; if (kmin < 0) kmin = 0;
    kmin &= ~31;
    int kmax = q0 + 127;

    int cj = tid & 31, dg = tid >> 5;
    const float* kr0 = k + ((size_t)(b * TT + cj) * NKV + kh) * HD + dg * 16;
    const float* vr0 = v + ((size_t)(b * TT + cj) * NKV + kh) * HD + dg * 16;

    for (int kt = kmin; kt <= kmax; kt += 32) {
        __syncthreads();
        {
            const float* krp = kr0 + (size_t)kt * NKV * HD;
            const float* vrp = vr0 + (size_t)kt * NKV * HD;
            #pragma unroll
            for (int u = 0; u < 4; u++) {
                float4 kv = *(const float4*)(krp + u * 4);
                float4 vv = *(const float4*)(vrp + u * 4);
                int d0 = dg * 16 + u * 4;
                Kt[(d0 + 0) * TSTR + cj] = kv.x; Kt[(d0 + 1) * TSTR + cj] = kv.y;
                Kt[(d0 + 2) * TSTR + cj] = kv.z; Kt[(d0 + 3) * TSTR + cj] = kv.w;
                Vt[(d0 + 0) * TSTR + cj] = vv.x; Vt[(d0 + 1) * TSTR + cj] = vv.y;
                Vt[(d0 + 2) * TSTR + cj] = vv.z; Vt[(d0 + 3) * TSTR + cj] = vv.w;
            }
        }
        __syncthreads();

        float S[2][4][4];
        #pragma unroll
        for (int mi = 0; mi < 2; mi++)
            #pragma unroll
            for (int nj = 0; nj < 4; nj++)
                #pragma unroll
                for (int c = 0; c < 4; c++) S[mi][nj][c] = 0.f;
        #pragma unroll
        for (int kk = 0; kk < 8; kk++) {
            uint32_t bf[4][2];
            #pragma unroll
            for (int nj = 0; nj < 4; nj++) {
                bf[nj][0] = f2tf(Kt[(kk * 8 + lc) * TSTR + nj * 8 + lr]);
                bf[nj][1] = f2tf(Kt[(kk * 8 + lc + 4) * TSTR + nj * 8 + lr]);
            }
            #pragma unroll
            for (int mi = 0; mi < 2; mi++)
                #pragma unroll
                for (int nj = 0; nj < 4; nj++)
                    mma8(S[mi][nj], Qf[mi][kk], bf[nj]);
        }

        #pragma unroll
        for (int mi = 0; mi < 2; mi++) {
            #pragma unroll
            for (int h2 = 0; h2 < 2; h2++) {
                int qi = qw + mi * 16 + h2 * 8 + lr;
                float tm = -1e30f;
                #pragma unroll
                for (int nj = 0; nj < 4; nj++) {
                    #pragma unroll
                    for (int c = 0; c < 2; c++) {
                        int j = kt + nj * 8 + lc * 2 + c;
                        bool ok = (j <= qi) && (j > qi - WIN);
                        float sv = ok ? S[mi][nj][h2 * 2 + c] : -1e30f;
                        S[mi][nj][h2 * 2 + c] = sv;
                        tm = fmaxf(tm, sv);
                    }
                }
                tm = fmaxf(tm, __shfl_xor_sync(~0u, tm, 1));
                tm = fmaxf(tm, __shfl_xor_sync(~0u, tm, 2));
                float mn = fmaxf(mrow[mi][h2], tm);
                float corr = __expf(mrow[mi][h2] - mn);
                #pragma unroll
                for (int ni = 0; ni < 8; ni++) {
                    O[mi][ni][h2 * 2 + 0] *= corr;
                    O[mi][ni][h2 * 2 + 1] *= corr;
                }
                float ls = 0.f;
                #pragma unroll
                for (int nj = 0; nj < 4; nj++) {
                    uint2 pp;
                    float sv0 = S[mi][nj][h2 * 2 + 0];
                    float sv1 = S[mi][nj][h2 * 2 + 1];
                    float p0 = (sv0 > -9e29f) ? __expf(sv0 - mn) : 0.f;
                    float p1 = (sv1 > -9e29f) ? __expf(sv1 - mn) : 0.f;
                    ls += p0 + p1;
                    pp.x = f2tf(p0); pp.y = f2tf(p1);
                    *(uint2*)&Psm[warp][(mi * 16 + h2 * 8 + lr) * TSTR + nj * 8 + lc * 2] = pp;
                }
                ls += __shfl_xor_sync(~0u, ls, 1);
                ls += __shfl_xor_sync(~0u, ls, 2);
                lrow[mi][h2] = lrow[mi][h2] * corr + ls;
                mrow[mi][h2] = mn;
            }
        }
        __syncwarp();

        #pragma unroll
        for (int kk = 0; kk < 4; kk++) {
            uint32_t a[2][4], bf[8][2];
            #pragma unroll
            for (int mi = 0; mi < 2; mi++) {
                const uint32_t* ap = &Psm[warp][(mi * 16 + lr) * TSTR + kk * 8 + lc];
                a[mi][0] = ap[0];
                a[mi][1] = ap[8 * TSTR];
                a[mi][2] = ap[4];
                a[mi][3] = ap[8 * TSTR + 4];
            }
            #pragma unroll
            for (int ni = 0; ni < 8; ni++) {
                bf[ni][0] = f2tf(Vt[(ni * 8 + lr) * TSTR + kk * 8 + lc]);
                bf[ni][1] = f2tf(Vt[(ni * 8 + lr) * TSTR + kk * 8 + lc + 4]);
            }
            #pragma unroll
            for (int mi = 0; mi < 2; mi++)
                #pragma unroll
                for (int ni = 0; ni < 8; ni++)
                    mma8(O[mi][ni], a[mi], bf[ni]);
        }
    }

    #pragma unroll
    for (int mi = 0; mi < 2; mi++) {
        #pragma unroll
        for (int h2 = 0; h2 < 2; h2++) {
            int qi = qw + mi * 16 + h2 * 8 + lr;
            float inv = 1.f / lrow[mi][h2];
            float* orow = out + ((size_t)(b * TT + qi) * NH + h) * HD;
            #pragma unroll
            for (int ni = 0; ni < 8; ni++) {
                float2 vv;
                vv.x = O[mi][ni][h2 * 2 + 0] * inv;
                vv.y = O[mi][ni][h2 * 2 + 1] * inv;
                *(float2*)(orow + ni * 8 + lc * 2) = vv;
            }
        }
    }
}

// ---------------- final combine ----------------
__global__ void combine_kernel(float* __restrict__ out) {
    int idx = blockIdx.x * blockDim.x + threadIdx.x;
    int n  = idx >> 8;
    int c4 = idx & 255;
    int e0 = g_tidx[n * 2], e1 = g_tidx[n * 2 + 1];
    int p0 = g_tpos[n * 2], p1 = g_tpos[n * 2 + 1];
    float w0 = g_twt[n * 2], w1 = g_twt[n * 2 + 1];
    float4 h4 = ((const float4*)g_hres)[idx];
    float4 a = ((const float4*)(g_moe + ((size_t)e0 * NTOK + p0) * CC))[c4];
    float4 b = ((const float4*)(g_moe + ((size_t)e1 * NTOK + p1) * CC))[c4];
    float4 o;
    o.x = h4.x + w0 * a.x + w1 * b.x;
    o.y = h4.y + w0 * a.y + w1 * b.y;
    o.z = h4.z + w0 * a.z + w1 * b.z;
    o.w = h4.w + w0 * a.w + w1 * b.w;
    ((float4*)out)[idx] = o;
}

// ---------------- launch ----------------
extern "C" void kernel_launch(void* const* d_in, const int* in_sizes, int n_in,
                              void* d_out, int out_size) {
    const float* x           = (const float*)d_in[0];
    const float* attn_norm_w = (const float*)d_in[1];
    const float* ffn_norm_w  = (const float*)d_in[2];
    const float* wq          = (const float*)d_in[3];
    const float* wk          = (const float*)d_in[4];
    const float* wv          = (const float*)d_in[5];
    const float* wo          = (const float*)d_in[6];
    const float* gate_w      = (const float*)d_in[7];
    const float* w1          = (const float*)d_in[8];
    const float* w2          = (const float*)d_in[9];
    const float* w3          = (const float*)d_in[10];
    float* out = (float*)d_out;

    cudaFuncSetAttribute(qkv_gemm,    cudaFuncAttributeMaxDynamicSharedMemorySize, SMEMG);
    cudaFuncSetAttribute(wo_gemm,     cudaFuncAttributeMaxDynamicSharedMemorySize, SMEMG);
    cudaFuncSetAttribute(moe13_fused, cudaFuncAttributeMaxDynamicSharedMemorySize, SMEM16);
    cudaFuncSetAttribute(moe2_gemm,   cudaFuncAttributeMaxDynamicSharedMemorySize, SMEM16);

    float *hn, *qb, *kb, *vb, *att, *hres;
    unsigned short *gb16;
    cudaGetSymbolAddress((void**)&hn,    g_hn);
    cudaGetSymbolAddress((void**)&qb,    g_q);
    cudaGetSymbolAddress((void**)&kb,    g_k);
    cudaGetSymbolAddress((void**)&vb,    g_v);
    cudaGetSymbolAddress((void**)&att,   g_att);
    cudaGetSymbolAddress((void**)&hres,  g_hres);
    cudaGetSymbolAddress((void**)&gb16,  g_gb16);

    // 1: weight transpose+convert (+ zero counts)
    transpose_all<<<dim3(4096, 1, 24), 256>>>(w1, w3, w2);
    // 2: attn rmsnorm
    rmsnorm_kernel<<<NTOK, 256>>>(x, attn_norm_w, hn, nullptr, nullptr);
    // 3: fused QKV projections
    qkv_gemm<<<dim3(12, 32), 256, SMEMG>>>(hn, wq, wk, wv);
    // 4: RoPE
    {
        int tot = NTOK * (NH + NKV) * 32;
        rope_all_kernel<<<(tot + 255) / 256, 256>>>(qb, kb);
    }
    // 5: tensor-core sliding-window attention
    attn_mma<<<dim3(TT / 128, BB * NH), 128>>>(qb, kb, vb, att);
    // 6: output projection + residual
    wo_gemm<<<dim3(8, 32), 256, SMEMG>>>(att, wo, hres, x);
    // 7: ffn rmsnorm + fused routing (bf16 out only; fp32 gbuf no longer needed)
    rmsnorm_kernel<<<NTOK, 256>>>(hres, ffn_norm_w, nullptr, gb16, gate_w);
    // 8: fused MoE pass 1+2 (R9 grid order: n fastest)
    moe13_fused<<<dim3(FF / 64, NTOK / 128, EE), 256, SMEM16>>>();
    // 9: MoE pass 3 (R9 grid order)
    moe2_gemm<<<dim3(CC / 128, NTOK / 128, EE), 256, SMEM16>>>();
    // 10: final combine + residual
    combine_kernel<<<(NTOK * CC / 4) / 256, 256>>>(out);
}

// round 13
// speedup vs baseline: 1.5601x; 1.1114x over previous
#include <cuda_runtime.h>
#include <cuda_bf16.h>
#include <cstdint>

// ---------------- problem constants ----------------
#define BB   4
#define TT   1024
#define CC   1024
#define NH   16
#define NKV  4
#define HD   64
#define EE   8
#define FF   4096
#define WIN  256
#define NTOK (BB*TT)          // 4096
#define EPS  1e-6f

// ---------------- scratch ----------------
__device__ float g_q   [(size_t)NTOK*NH*HD];
__device__ float g_k   [(size_t)NTOK*NKV*HD];
__device__ float g_v   [(size_t)NTOK*NKV*HD];
__device__ float g_hres[(size_t)NTOK*CC];
__device__ int   g_counts[EE];
__device__ int   g_tok [(size_t)EE*NTOK];
__device__ int   g_tidx[(size_t)NTOK*2];
__device__ int   g_tpos[(size_t)NTOK*2];
__device__ float g_twt [(size_t)NTOK*2];
__device__ float g_moe [(size_t)EE*NTOK*CC];
__device__ unsigned short g_hn16 [(size_t)NTOK*CC];
__device__ unsigned short g_att16[(size_t)NTOK*CC];
__device__ unsigned short g_gb16 [(size_t)NTOK*CC];
__device__ unsigned short g_hid16[(size_t)EE*NTOK*FF];
__device__ unsigned short g_w1t  [(size_t)EE*CC*FF];    // [e][FF][CC] bf16
__device__ unsigned short g_w3t  [(size_t)EE*CC*FF];
__device__ unsigned short g_w2t  [(size_t)EE*FF*CC];    // [e][CC][FF] bf16
__device__ unsigned short g_wqt  [(size_t)CC*NH*HD];    // [N][K] bf16
__device__ unsigned short g_wkt  [(size_t)CC*NKV*HD];
__device__ unsigned short g_wvt  [(size_t)CC*NKV*HD];
__device__ unsigned short g_wot  [(size_t)CC*CC];

// ---------------- helpers ----------------
__device__ __forceinline__ uint32_t smem_u32(const void* p) {
    uint32_t a;
    asm("{ .reg .u64 t; cvta.to.shared.u64 t, %1; cvt.u32.u64 %0, t; }" : "=r"(a) : "l"(p));
    return a;
}
__device__ __forceinline__ void cp16(uint32_t dst, const void* src) {
    asm volatile("cp.async.cg.shared.global [%0], [%1], 16;" :: "r"(dst), "l"(src));
}
__device__ __forceinline__ void cp_commit() { asm volatile("cp.async.commit_group;" ::: "memory"); }
__device__ __forceinline__ void cp_wait2() { asm volatile("cp.async.wait_group 2;" ::: "memory"); }
__device__ __forceinline__ uint32_t f2tf(float f) {
    uint32_t r; asm("cvt.rna.tf32.f32 %0, %1;" : "=r"(r) : "f"(f)); return r;
}
__device__ __forceinline__ void mma8(float* c, const uint32_t* a, const uint32_t* b) {
    asm volatile("mma.sync.aligned.m16n8k8.row.col.f32.tf32.tf32.f32 "
                 "{%0,%1,%2,%3}, {%4,%5,%6,%7}, {%8,%9}, {%0,%1,%2,%3};"
                 : "+f"(c[0]), "+f"(c[1]), "+f"(c[2]), "+f"(c[3])
                 : "r"(a[0]), "r"(a[1]), "r"(a[2]), "r"(a[3]), "r"(b[0]), "r"(b[1]));
}
__device__ __forceinline__ void mma16(float* c, const uint32_t* a, const uint32_t* b) {
    asm volatile("mma.sync.aligned.m16n8k16.row.col.f32.bf16.bf16.f32 "
                 "{%0,%1,%2,%3}, {%4,%5,%6,%7}, {%8,%9}, {%0,%1,%2,%3};"
                 : "+f"(c[0]), "+f"(c[1]), "+f"(c[2]), "+f"(c[3])
                 : "r"(a[0]), "r"(a[1]), "r"(a[2]), "r"(a[3]), "r"(b[0]), "r"(b[1]));
}
__device__ __forceinline__ void ldsm4(uint32_t* r, uint32_t addr) {
    asm volatile("ldmatrix.sync.aligned.m8n8.x4.shared.b16 {%0,%1,%2,%3}, [%4];"
                 : "=r"(r[0]), "=r"(r[1]), "=r"(r[2]), "=r"(r[3]) : "r"(addr));
}

// ================= bf16 GEMM core (ldmatrix) =================
#define HROW 80
#define HTILE_B (128*HROW)
#define NS16 4
#define SMEM16 (NS16*2*HTILE_B)    // 81920 bytes

struct Bf16Loop {
    uint32_t sbase;
    int lane, wm, wn;
    uint32_t aR, aK, bR, bK;
    __device__ __forceinline__ void init(uint32_t sb, int tid) {
        sbase = sb;
        lane = tid & 31;
        int warp = tid >> 5;
        wm = warp & 3; wn = warp >> 2;
        aR = (lane & 7) + ((lane >> 3) & 1) * 8;
        aK = ((lane >> 4) & 1) * 16;
        bR = (lane & 7) + ((lane >> 4) & 1) * 8;
        bK = ((lane >> 3) & 1) * 16;
    }
    __device__ __forceinline__ void compute(int p, float acc[2][8][4]) {
        uint32_t Am = sbase + p * (2 * HTILE_B);
        uint32_t Bm = Am + HTILE_B;
        #pragma unroll
        for (int kk = 0; kk < 2; kk++) {
            uint32_t a[2][4], b[4][4];
            #pragma unroll
            for (int mi = 0; mi < 2; mi++)
                ldsm4(a[mi], Am + (wm * 32 + mi * 16 + aR) * HROW + kk * 32 + aK);
            #pragma unroll
            for (int p2 = 0; p2 < 4; p2++)
                ldsm4(b[p2], Bm + (wn * 64 + p2 * 16 + bR) * HROW + kk * 32 + bK);
            #pragma unroll
            for (int mi = 0; mi < 2; mi++)
                #pragma unroll
                for (int ni = 0; ni < 8; ni++)
                    mma16(acc[mi][ni], a[mi], &b[ni >> 1][(ni & 1) * 2]);
        }
    }
};

// dense bf16 GEMM body: C(f32)[m][nloc..] = A16[m][K] @ Wt16[n][K]^T (+res)
__device__ __forceinline__ void gemm_body_bf16(
    const unsigned short* __restrict__ A, const unsigned short* __restrict__ Wt,
    float* __restrict__ C, const float* __restrict__ res,
    int K, int Nw, int m0, int nloc, char* smraw)
{
    int tid = threadIdx.x;
    uint32_t sbase = smem_u32(smraw);
    Bf16Loop L; L.init(sbase, tid);

    int row = tid >> 1, sl = (tid & 1) * 2;
    const unsigned short* arow = A + (size_t)(m0 + row) * K;
    const unsigned short* brow = Wt + (size_t)(nloc + row) * K;

    uint32_t aD[NS16], bD[NS16];
    #pragma unroll
    for (int s = 0; s < NS16; s++) {
        aD[s] = sbase + s * (2 * HTILE_B) + row * HROW + sl * 16;
        bD[s] = aD[s] + HTILE_B;
    }
    auto load_chunk = [&](int ci, int p) {
        const unsigned short* as = arow + ci * 32 + sl * 8;
        cp16(aD[p], as); cp16(aD[p] + 16, as + 8);
        const unsigned short* bs = brow + ci * 32 + sl * 8;
        cp16(bD[p], bs); cp16(bD[p] + 16, bs + 8);
    };

    float acc[2][8][4];
    #pragma unroll
    for (int mi = 0; mi < 2; mi++)
        #pragma unroll
        for (int ni = 0; ni < 8; ni++)
            #pragma unroll
            for (int q = 0; q < 4; q++) acc[mi][ni][q] = 0.f;

    int NC = K / 32;
    load_chunk(0, 0); cp_commit();
    load_chunk(1, 1); cp_commit();
    load_chunk(2, 2); cp_commit();
    for (int i = 0; i < NC; i++) {
        cp_wait2();
        __syncthreads();
        int nx = i + NS16 - 1;
        if (nx < NC) load_chunk(nx, nx % NS16);
        cp_commit();
        L.compute(i % NS16, acc);
    }

    int lr = L.lane >> 2, lc = L.lane & 3;
    #pragma unroll
    for (int mi = 0; mi < 2; mi++)
        #pragma unroll
        for (int half = 0; half < 2; half++) {
            int m = m0 + L.wm * 32 + mi * 16 + half * 8 + lr;
            float* crow = C + (size_t)m * Nw + nloc + L.wn * 64;
            #pragma unroll
            for (int ni = 0; ni < 8; ni++) {
                float c0 = acc[mi][ni][half * 2 + 0];
                float c1 = acc[mi][ni][half * 2 + 1];
                if (res) {
                    const float2 rr = *(const float2*)(res + (size_t)m * Nw + nloc + L.wn * 64 + ni * 8 + lc * 2);
                    c0 += rr.x; c1 += rr.y;
                }
                float2 v; v.x = c0; v.y = c1;
                *(float2*)(crow + ni * 8 + lc * 2) = v;
            }
        }
}

// fused QKV (bf16)
__global__ __launch_bounds__(256, 2)
void qkv16_gemm()
{
    extern __shared__ char smraw[];
    int m0 = blockIdx.y * 128;
    int nb = blockIdx.x;
    const unsigned short* Wt; float* O; int Nw, nloc;
    if (nb < 8)       { Wt = g_wqt; O = g_q; Nw = NH * HD;  nloc = nb * 128; }
    else if (nb < 10) { Wt = g_wkt; O = g_k; Nw = NKV * HD; nloc = (nb - 8) * 128; }
    else              { Wt = g_wvt; O = g_v; Nw = NKV * HD; nloc = (nb - 10) * 128; }
    gemm_body_bf16(g_hn16, Wt, O, (const float*)0, CC, Nw, m0, nloc, smraw);
}

// wo projection + residual (bf16)
__global__ __launch_bounds__(256, 2)
void wo16_gemm(const float* __restrict__ res)
{
    extern __shared__ char smraw[];
    gemm_body_bf16(g_att16, g_wot, g_hres, res, CC, CC,
                   blockIdx.y * 128, blockIdx.x * 128, smraw);
}

// ---- fused MoE pass 1+2 (n-block fastest) ----
__global__ __launch_bounds__(256, 2)
void moe13_fused()
{
    int e = blockIdx.z;
    int cnt = g_counts[e];
    int m0 = blockIdx.y * 128;
    if (m0 >= cnt) return;
    int c0 = blockIdx.x * 64;

    extern __shared__ char smraw[];
    int tid = threadIdx.x;
    uint32_t sbase = smem_u32(smraw);
    Bf16Loop L; L.init(sbase, tid);

    int row = tid >> 1, sl = (tid & 1) * 2;
    const unsigned short* arow;
    {
        int grow = m0 + row;
        int g2 = (grow < cnt) ? grow : 0;
        arow = g_gb16 + (size_t)g_tok[e * NTOK + g2] * CC;
    }
    const unsigned short* brow = (row < 64)
        ? g_w1t + (size_t)e * CC * FF + (size_t)(c0 + row) * CC
        : g_w3t + (size_t)e * CC * FF + (size_t)(c0 + row - 64) * CC;

    uint32_t aD[NS16], bD[NS16];
    #pragma unroll
    for (int s = 0; s < NS16; s++) {
        aD[s] = sbase + s * (2 * HTILE_B) + row * HROW + sl * 16;
        bD[s] = aD[s] + HTILE_B;
    }
    auto load_chunk = [&](int ci, int p) {
        const unsigned short* as = arow + ci * 32 + sl * 8;
        cp16(aD[p], as); cp16(aD[p] + 16, as + 8);
        const unsigned short* bs = brow + ci * 32 + sl * 8;
        cp16(bD[p], bs); cp16(bD[p] + 16, bs + 8);
    };

    float acc[2][8][4];
    #pragma unroll
    for (int mi = 0; mi < 2; mi++)
        #pragma unroll
        for (int ni = 0; ni < 8; ni++)
            #pragma unroll
            for (int q = 0; q < 4; q++) acc[mi][ni][q] = 0.f;

    const int NC = CC / 32;
    load_chunk(0, 0); cp_commit();
    load_chunk(1, 1); cp_commit();
    load_chunk(2, 2); cp_commit();
    for (int i = 0; i < NC; i++) {
        cp_wait2();
        __syncthreads();
        int nx = i + NS16 - 1;
        if (nx < NC) load_chunk(nx, nx % NS16);
        cp_commit();
        L.compute(i % NS16, acc);
    }

    __syncthreads();
    float* eps = (float*)smraw;
    int lr = L.lane >> 2, lc = L.lane & 3;
    if (L.wn == 1) {
        #pragma unroll
        for (int mi = 0; mi < 2; mi++)
            #pragma unroll
            for (int half = 0; half < 2; half++) {
                int ml = L.wm * 32 + mi * 16 + half * 8 + lr;
                #pragma unroll
                for (int ni = 0; ni < 8; ni++) {
                    eps[ml * 66 + ni * 8 + lc * 2 + 0] = acc[mi][ni][half * 2 + 0];
                    eps[ml * 66 + ni * 8 + lc * 2 + 1] = acc[mi][ni][half * 2 + 1];
                }
            }
    }
    __syncthreads();
    if (L.wn == 0) {
        unsigned short* hrow = g_hid16 + (size_t)e * NTOK * FF + c0;
        #pragma unroll
        for (int mi = 0; mi < 2; mi++)
            #pragma unroll
            for (int half = 0; half < 2; half++) {
                int ml = L.wm * 32 + mi * 16 + half * 8 + lr;
                int m = m0 + ml;
                if (m < cnt) {
                    #pragma unroll
                    for (int ni = 0; ni < 8; ni++) {
                        float x0 = acc[mi][ni][half * 2 + 0];
                        float x1 = acc[mi][ni][half * 2 + 1];
                        float a3x = eps[ml * 66 + ni * 8 + lc * 2 + 0];
                        float a3y = eps[ml * 66 + ni * 8 + lc * 2 + 1];
                        float v0 = x0 / (1.f + __expf(-x0)) * a3x;
                        float v1 = x1 / (1.f + __expf(-x1)) * a3y;
                        __nv_bfloat162 o(__float2bfloat16_rn(v0), __float2bfloat16_rn(v1));
                        *(__nv_bfloat162*)(hrow + (size_t)m * FF + ni * 8 + lc * 2) = o;
                    }
                }
            }
    }
}

// ---- MoE pass 3 ----
__global__ __launch_bounds__(256, 2)
void moe2_gemm()
{
    int e = blockIdx.z;
    int cnt = g_counts[e];
    int m0 = blockIdx.y * 128;
    if (m0 >= cnt) return;
    int n0 = blockIdx.x * 128;

    extern __shared__ char smraw[];
    int tid = threadIdx.x;
    uint32_t sbase = smem_u32(smraw);
    Bf16Loop L; L.init(sbase, tid);

    int row = tid >> 1, sl = (tid & 1) * 2;
    const unsigned short* arow = g_hid16 + (size_t)e * NTOK * FF + (size_t)(m0 + row) * FF;
    const unsigned short* brow = g_w2t + (size_t)e * FF * CC + (size_t)(n0 + row) * FF;

    uint32_t aD[NS16], bD[NS16];
    #pragma unroll
    for (int s = 0; s < NS16; s++) {
        aD[s] = sbase + s * (2 * HTILE_B) + row * HROW + sl * 16;
        bD[s] = aD[s] + HTILE_B;
    }
    auto load_chunk = [&](int ci, int p) {
        const unsigned short* as = arow + ci * 32 + sl * 8;
        cp16(aD[p], as); cp16(aD[p] + 16, as + 8);
        const unsigned short* bs = brow + ci * 32 + sl * 8;
        cp16(bD[p], bs); cp16(bD[p] + 16, bs + 8);
    };

    float acc[2][8][4];
    #pragma unroll
    for (int mi = 0; mi < 2; mi++)
        #pragma unroll
        for (int ni = 0; ni < 8; ni++)
            #pragma unroll
            for (int q = 0; q < 4; q++) acc[mi][ni][q] = 0.f;

    const int NC = FF / 32;
    load_chunk(0, 0); cp_commit();
    load_chunk(1, 1); cp_commit();
    load_chunk(2, 2); cp_commit();
    for (int i = 0; i < NC; i++) {
        cp_wait2();
        __syncthreads();
        int nx = i + NS16 - 1;
        if (nx < NC) load_chunk(nx, nx % NS16);
        cp_commit();
        L.compute(i % NS16, acc);
    }

    int lr = L.lane >> 2, lc = L.lane & 3;
    float* Co = g_moe + (size_t)e * NTOK * CC;
    #pragma unroll
    for (int mi = 0; mi < 2; mi++)
        #pragma unroll
        for (int half = 0; half < 2; half++) {
            int m = m0 + L.wm * 32 + mi * 16 + half * 8 + lr;
            if (m < cnt) {
                #pragma unroll
                for (int ni = 0; ni < 8; ni++) {
                    float2 v;
                    v.x = acc[mi][ni][half * 2 + 0];
                    v.y = acc[mi][ni][half * 2 + 1];
                    *(float2*)(Co + (size_t)m * CC + n0 + L.wn * 64 + ni * 8 + lc * 2) = v;
                }
            }
        }
}

// ---------------- weight transpose+convert (all weights, + zero counts) ----------------
__global__ void transpose_all(const float* __restrict__ w1, const float* __restrict__ w3,
                              const float* __restrict__ w2, const float* __restrict__ wq,
                              const float* __restrict__ wk, const float* __restrict__ wv,
                              const float* __restrict__ wo) {
    if (blockIdx.x == 0 && blockIdx.z == 0 && threadIdx.x < EE)
        g_counts[threadIdx.x] = 0;
    __shared__ float t[32][33];
    int z = blockIdx.z;
    const float* src; unsigned short* dst; int K, N;
    if (z < 8)       { src = w1 + (size_t)z * CC * FF;        dst = g_w1t + (size_t)z * CC * FF;        K = CC; N = FF; }
    else if (z < 16) { src = w3 + (size_t)(z - 8) * CC * FF;  dst = g_w3t + (size_t)(z - 8) * CC * FF;  K = CC; N = FF; }
    else if (z < 24) { src = w2 + (size_t)(z - 16) * FF * CC; dst = g_w2t + (size_t)(z - 16) * FF * CC; K = FF; N = CC; }
    else if (z == 24){ src = wq; dst = g_wqt; K = CC; N = NH * HD; }
    else if (z == 25){ src = wk; dst = g_wkt; K = CC; N = NKV * HD; }
    else if (z == 26){ src = wv; dst = g_wvt; K = CC; N = NKV * HD; }
    else             { src = wo; dst = g_wot; K = CC; N = CC; }
    int nb = N / 32;
    int tot = (K / 32) * nb;
    if ((int)blockIdx.x >= tot) return;
    int n0 = (blockIdx.x % nb) * 32;
    int k0 = (blockIdx.x / nb) * 32;
    int tx = threadIdx.x & 31, ty = threadIdx.x >> 5;
    #pragma unroll
    for (int p = 0; p < 4; p++)
        t[ty + p * 8][tx] = src[(size_t)(k0 + ty + p * 8) * N + n0 + tx];
    __syncthreads();
    #pragma unroll
    for (int p = 0; p < 4; p++) {
        __nv_bfloat16 v = __float2bfloat16_rn(t[tx][ty + p * 8]);
        dst[(size_t)(n0 + ty + p * 8) * K + k0 + tx] = *(unsigned short*)&v;
    }
}

// ---------------- rmsnorm (+ optional fused MoE routing) ----------------
__global__ void rmsnorm_kernel(const float* __restrict__ x,
                               const float* __restrict__ w,
                               unsigned short* __restrict__ o16,
                               const float* __restrict__ gw) {
    int row = blockIdx.x;
    const float* xr = x + (size_t)row * CC;
    __shared__ float red[8];
    __shared__ float gred[8][EE];
    float s = 0.f;
    for (int c = threadIdx.x; c < CC; c += 256) { float v = xr[c]; s += v * v; }
    #pragma unroll
    for (int off = 16; off; off >>= 1) s += __shfl_xor_sync(~0u, s, off);
    if ((threadIdx.x & 31) == 0) red[threadIdx.x >> 5] = s;
    __syncthreads();
    if (threadIdx.x < 8) {
        float t = red[threadIdx.x];
        #pragma unroll
        for (int off = 4; off; off >>= 1) t += __shfl_xor_sync(0xff, t, off);
        if (threadIdx.x == 0) red[0] = t;
    }
    __syncthreads();
    float inv = rsqrtf(red[0] * (1.0f / CC) + EPS);
    float la[EE];
    #pragma unroll
    for (int e = 0; e < EE; e++) la[e] = 0.f;
    for (int c = threadIdx.x; c < CC; c += 256) {
        float v = xr[c] * inv * w[c];
        __nv_bfloat16 h = __float2bfloat16_rn(v);
        o16[(size_t)row * CC + c] = *(unsigned short*)&h;
        if (gw) {
            #pragma unroll
            for (int e = 0; e < EE; e++) la[e] += v * gw[c * EE + e];
        }
    }
    if (gw) {
        #pragma unroll
        for (int e = 0; e < EE; e++)
            #pragma unroll
            for (int off = 16; off; off >>= 1)
                la[e] += __shfl_xor_sync(~0u, la[e], off);
        if ((threadIdx.x & 31) == 0) {
            #pragma unroll
            for (int e = 0; e < EE; e++) gred[threadIdx.x >> 5][e] = la[e];
        }
        __syncthreads();
        if (threadIdx.x == 0) {
            float acc[EE];
            #pragma unroll
            for (int e = 0; e < EE; e++) {
                float t = 0.f;
                #pragma unroll
                for (int wq2 = 0; wq2 < 8; wq2++) t += gred[wq2][e];
                acc[e] = t;
            }
            int i0 = 0;
            #pragma unroll
            for (int e = 1; e < EE; e++) if (acc[e] > acc[i0]) i0 = e;
            int i1 = -1;
            #pragma unroll
            for (int e = 0; e < EE; e++)
                if (e != i0 && (i1 < 0 || acc[e] > acc[i1])) i1 = e;
            float p1 = __expf(acc[i1] - acc[i0]);
            float sw = 1.0f + p1;
            float w0 = 1.0f / sw, w1 = p1 / sw;
            int pos0 = atomicAdd(&g_counts[i0], 1);
            int pos1 = atomicAdd(&g_counts[i1], 1);
            g_tok[i0 * NTOK + pos0] = row;
            g_tok[i1 * NTOK + pos1] = row;
            g_tidx[row * 2 + 0] = i0; g_tidx[row * 2 + 1] = i1;
            g_tpos[row * 2 + 0] = pos0; g_tpos[row * 2 + 1] = pos1;
            g_twt [row * 2 + 0] = w0;  g_twt [row * 2 + 1] = w1;
        }
    }
}

__global__ void rope_all_kernel(float* __restrict__ q, float* __restrict__ k) {
    int idx = blockIdx.x * blockDim.x + threadIdx.x;
    const int qtot = NTOK * NH * 32;
    const int ktot = NTOK * NKV * 32;
    float* t; int nh;
    if (idx < qtot) { t = q; nh = NH; }
    else { idx -= qtot; if (idx >= ktot) return; t = k; nh = NKV; }
    int n = idx / (nh * 32);
    int r = idx - n * (nh * 32);
    int h = r >> 5;
    int d = r & 31;
    int pos = n & (TT - 1);
    float* p = t + ((size_t)n * nh + h) * HD;
    float fr  = __powf(10000.0f, -(float)d * (1.0f / 32.0f));
    float ang = (float)pos * fr;
    float cs = cosf(ang), sn = sinf(ang);
    float x1 = p[d], x2 = p[d + 32];
    p[d]      = x1 * cs - x2 * sn;
    p[d + 32] = x2 * cs + x1 * sn;
}

// ---------------- tensor-core flash attention (tf32) ----------------
#define TSTR 40

__global__ __launch_bounds__(128, 2)
void attn_mma(const float* __restrict__ q, const float* __restrict__ k,
              const float* __restrict__ v)
{
    __shared__ float Kt[64 * TSTR];          // [d][j]
    __shared__ float Vt[64 * TSTR];          // [d][j]
    __shared__ uint32_t Psm[4][32 * TSTR];   // per-warp P (tf32 bits)

    int bh = blockIdx.y;
    int b = bh >> 4, h = bh & 15;
    int kh = h >> 2;
    int q0 = blockIdx.x * 128;
    int tid = threadIdx.x;
    int warp = tid >> 5, lane = tid & 31;
    int lr = lane >> 2, lc = lane & 3;
    int qw = q0 + warp * 32;

    uint32_t Qf[2][8][4];
    #pragma unroll
    for (int mi = 0; mi < 2; mi++) {
        const float* qp0 = q + ((size_t)(b * TT + qw + mi * 16 + lr) * NH + h) * HD;
        const float* qp1 = qp0 + (size_t)8 * NH * HD;
        #pragma unroll
        for (int kk = 0; kk < 8; kk++) {
            Qf[mi][kk][0] = f2tf(qp0[kk * 8 + lc] * 0.125f);
            Qf[mi][kk][1] = f2tf(qp1[kk * 8 + lc] * 0.125f);
            Qf[mi][kk][2] = f2tf(qp0[kk * 8 + lc + 4] * 0.125f);
            Qf[mi][kk][3] = f2tf(qp1[kk * 8 + lc + 4] * 0.125f);
        }
    }

    float O[2][8][4];
    #pragma unroll
    for (int mi = 0; mi < 2; mi++)
        #pragma unroll
        for (int ni = 0; ni < 8; ni++)
            #pragma unroll
            for (int c = 0; c < 4; c++) O[mi][ni][c] = 0.f;
    float mrow[2][2] = { {-1e30f, -1e30f}, {-1e30f, -1e30f} };
    float lrow[2][2] = { {0.f, 0.f}, {0.f, 0.f} };

    int kmin = q0 - WIN + 1; if (kmin < 0) kmin = 0;
    kmin &= ~31;
    int kmax = q0 + 127;

    int cj = tid & 31, dg = tid >> 5;
    const float* kr0 = k + ((size_t)(b * TT + cj) * NKV + kh) * HD + dg * 16;
    const float* vr0 = v + ((size_t)(b * TT + cj) * NKV + kh) * HD + dg * 16;

    for (int kt = kmin; kt <= kmax; kt += 32) {
        __syncthreads();
        {
            const float* krp = kr0 + (size_t)kt * NKV * HD;
            const float* vrp = vr0 + (size_t)kt * NKV * HD;
            #pragma unroll
            for (int u = 0; u < 4; u++) {
                float4 kv = *(const float4*)(krp + u * 4);
                float4 vv = *(const float4*)(vrp + u * 4);
                int d0 = dg * 16 + u * 4;
                Kt[(d0 + 0) * TSTR + cj] = kv.x; Kt[(d0 + 1) * TSTR + cj] = kv.y;
                Kt[(d0 + 2) * TSTR + cj] = kv.z; Kt[(d0 + 3) * TSTR + cj] = kv.w;
                Vt[(d0 + 0) * TSTR + cj] = vv.x; Vt[(d0 + 1) * TSTR + cj] = vv.y;
                Vt[(d0 + 2) * TSTR + cj] = vv.z; Vt[(d0 + 3) * TSTR + cj] = vv.w;
            }
        }
        __syncthreads();

        float S[2][4][4];
        #pragma unroll
        for (int mi = 0; mi < 2; mi++)
            #pragma unroll
            for (int nj = 0; nj < 4; nj++)
                #pragma unroll
                for (int c = 0; c < 4; c++) S[mi][nj][c] = 0.f;
        #pragma unroll
        for (int kk = 0; kk < 8; kk++) {
            uint32_t bf[4][2];
            #pragma unroll
            for (int nj = 0; nj < 4; nj++) {
                bf[nj][0] = f2tf(Kt[(kk * 8 + lc) * TSTR + nj * 8 + lr]);
                bf[nj][1] = f2tf(Kt[(kk * 8 + lc + 4) * TSTR + nj * 8 + lr]);
            }
            #pragma unroll
            for (int mi = 0; mi < 2; mi++)
                #pragma unroll
                for (int nj = 0; nj < 4; nj++)
                    mma8(S[mi][nj], Qf[mi][kk], bf[nj]);
        }

        #pragma unroll
        for (int mi = 0; mi < 2; mi++) {
            #pragma unroll
            for (int h2 = 0; h2 < 2; h2++) {
                int qi = qw + mi * 16 + h2 * 8 + lr;
                float tm = -1e30f;
                #pragma unroll
                for (int nj = 0; nj < 4; nj++) {
                    #pragma unroll
                    for (int c = 0; c < 2; c++) {
                        int j = kt + nj * 8 + lc * 2 + c;
                        bool ok = (j <= qi) && (j > qi - WIN);
                        float sv = ok ? S[mi][nj][h2 * 2 + c] : -1e30f;
                        S[mi][nj][h2 * 2 + c] = sv;
                        tm = fmaxf(tm, sv);
                    }
                }
                tm = fmaxf(tm, __shfl_xor_sync(~0u, tm, 1));
                tm = fmaxf(tm, __shfl_xor_sync(~0u, tm, 2));
                float mn = fmaxf(mrow[mi][h2], tm);
                float corr = __expf(mrow[mi][h2] - mn);
                #pragma unroll
                for (int ni = 0; ni < 8; ni++) {
                    O[mi][ni][h2 * 2 + 0] *= corr;
                    O[mi][ni][h2 * 2 + 1] *= corr;
                }
                float ls = 0.f;
                #pragma unroll
                for (int nj = 0; nj < 4; nj++) {
                    uint2 pp;
                    float sv0 = S[mi][nj][h2 * 2 + 0];
                    float sv1 = S[mi][nj][h2 * 2 + 1];
                    float p0 = (sv0 > -9e29f) ? __expf(sv0 - mn) : 0.f;
                    float p1 = (sv1 > -9e29f) ? __expf(sv1 - mn) : 0.f;
                    ls += p0 + p1;
                    pp.x = f2tf(p0); pp.y = f2tf(p1);
                    *(uint2*)&Psm[warp][(mi * 16 + h2 * 8 + lr) * TSTR + nj * 8 + lc * 2] = pp;
                }
                ls += __shfl_xor_sync(~0u, ls, 1);
                ls += __shfl_xor_sync(~0u, ls, 2);
                lrow[mi][h2] = lrow[mi][h2] * corr + ls;
                mrow[mi][h2] = mn;
            }
        }
        __syncwarp();

        #pragma unroll
        for (int kk = 0; kk < 4; kk++) {
            uint32_t a[2][4], bf[8][2];
            #pragma unroll
            for (int mi = 0; mi < 2; mi++) {
                const uint32_t* ap = &Psm[warp][(mi * 16 + lr) * TSTR + kk * 8 + lc];
                a[mi][0] = ap[0];
                a[mi][1] = ap[8 * TSTR];
                a[mi][2] = ap[4];
                a[mi][3] = ap[8 * TSTR + 4];
            }
            #pragma unroll
            for (int ni = 0; ni < 8; ni++) {
                bf[ni][0] = f2tf(Vt[(ni * 8 + lr) * TSTR + kk * 8 + lc]);
                bf[ni][1] = f2tf(Vt[(ni * 8 + lr) * TSTR + kk * 8 + lc + 4]);
            }
            #pragma unroll
            for (int mi = 0; mi < 2; mi++)
                #pragma unroll
                for (int ni = 0; ni < 8; ni++)
                    mma8(O[mi][ni], a[mi], bf[ni]);
        }
    }

    // epilogue: write att as bf16 for the wo GEMM
    #pragma unroll
    for (int mi = 0; mi < 2; mi++) {
        #pragma unroll
        for (int h2 = 0; h2 < 2; h2++) {
            int qi = qw + mi * 16 + h2 * 8 + lr;
            float inv = 1.f / lrow[mi][h2];
            unsigned short* orow = g_att16 + ((size_t)(b * TT + qi) * NH + h) * HD;
            #pragma unroll
            for (int ni = 0; ni < 8; ni++) {
                float vx = O[mi][ni][h2 * 2 + 0] * inv;
                float vy = O[mi][ni][h2 * 2 + 1] * inv;
                __nv_bfloat162 o(__float2bfloat16_rn(vx), __float2bfloat16_rn(vy));
                *(__nv_bfloat162*)(orow + ni * 8 + lc * 2) = o;
            }
        }
    }
}

// ---------------- final combine ----------------
__global__ void combine_kernel(float* __restrict__ out) {
    int idx = blockIdx.x * blockDim.x + threadIdx.x;
    int n  = idx >> 8;
    int c4 = idx & 255;
    int e0 = g_tidx[n * 2], e1 = g_tidx[n * 2 + 1];
    int p0 = g_tpos[n * 2], p1 = g_tpos[n * 2 + 1];
    float w0 = g_twt[n * 2], w1 = g_twt[n * 2 + 1];
    float4 h4 = ((const float4*)g_hres)[idx];
    float4 a = ((const float4*)(g_moe + ((size_t)e0 * NTOK + p0) * CC))[c4];
    float4 b = ((const float4*)(g_moe + ((size_t)e1 * NTOK + p1) * CC))[c4];
    float4 o;
    o.x = h4.x + w0 * a.x + w1 * b.x;
    o.y = h4.y + w0 * a.y + w1 * b.y;
    o.z = h4.z + w0 * a.z + w1 * b.z;
    o.w = h4.w + w0 * a.w + w1 * b.w;
    ((float4*)out)[idx] = o;
}

// ---------------- launch ----------------
extern "C" void kernel_launch(void* const* d_in, const int* in_sizes, int n_in,
                              void* d_out, int out_size) {
    const float* x           = (const float*)d_in[0];
    const float* attn_norm_w = (const float*)d_in[1];
    const float* ffn_norm_w  = (const float*)d_in[2];
    const float* wq          = (const float*)d_in[3];
    const float* wk          = (const float*)d_in[4];
    const float* wv          = (const float*)d_in[5];
    const float* wo          = (const float*)d_in[6];
    const float* gate_w      = (const float*)d_in[7];
    const float* w1          = (const float*)d_in[8];
    const float* w2          = (const float*)d_in[9];
    const float* w3          = (const float*)d_in[10];
    float* out = (float*)d_out;

    cudaFuncSetAttribute(qkv16_gemm,  cudaFuncAttributeMaxDynamicSharedMemorySize, SMEM16);
    cudaFuncSetAttribute(wo16_gemm,   cudaFuncAttributeMaxDynamicSharedMemorySize, SMEM16);
    cudaFuncSetAttribute(moe13_fused, cudaFuncAttributeMaxDynamicSharedMemorySize, SMEM16);
    cudaFuncSetAttribute(moe2_gemm,   cudaFuncAttributeMaxDynamicSharedMemorySize, SMEM16);

    float *qb, *kb, *vb, *hres;
    unsigned short *hn16, *gb16;
    cudaGetSymbolAddress((void**)&qb,    g_q);
    cudaGetSymbolAddress((void**)&kb,    g_k);
    cudaGetSymbolAddress((void**)&vb,    g_v);
    cudaGetSymbolAddress((void**)&hres,  g_hres);
    cudaGetSymbolAddress((void**)&hn16,  g_hn16);
    cudaGetSymbolAddress((void**)&gb16,  g_gb16);

    // 1: weight transpose+convert (all weights, + zero counts)
    transpose_all<<<dim3(4096, 1, 28), 256>>>(w1, w3, w2, wq, wk, wv, wo);
    // 2: attn rmsnorm (bf16 out)
    rmsnorm_kernel<<<NTOK, 256>>>(x, attn_norm_w, hn16, nullptr);
    // 3: fused QKV projections (bf16)
    qkv16_gemm<<<dim3(12, 32), 256, SMEM16>>>();
    // 4: RoPE
    {
        int tot = NTOK * (NH + NKV) * 32;
        rope_all_kernel<<<(tot + 255) / 256, 256>>>(qb, kb);
    }
    // 5: tensor-core sliding-window attention (emits bf16 att)
    attn_mma<<<dim3(TT / 128, BB * NH), 128>>>(qb, kb, vb);
    // 6: output projection + residual (bf16)
    wo16_gemm<<<dim3(8, 32), 256, SMEM16>>>(x);
    // 7: ffn rmsnorm + fused routing
    rmsnorm_kernel<<<NTOK, 256>>>(hres, ffn_norm_w, gb16, gate_w);
    // 8: fused MoE pass 1+2
    moe13_fused<<<dim3(FF / 64, NTOK / 128, EE), 256, SMEM16>>>();
    // 9: MoE pass 3
    moe2_gemm<<<dim3(CC / 128, NTOK / 128, EE), 256, SMEM16>>>();
    // 10: final combine + residual
    combine_kernel<<<(NTOK * CC / 4) / 256, 256>>>(out);
}

// round 16
// speedup vs baseline: 1.5889x; 1.0185x over previous
#include <cuda_runtime.h>
#include <cuda_bf16.h>
#include <cstdint>

// ---------------- problem constants ----------------
#define BB   4
#define TT   1024
#define CC   1024
#define NH   16
#define NKV  4
#define HD   64
#define EE   8
#define FF   4096
#define WIN  256
#define NTOK (BB*TT)          // 4096
#define EPS  1e-6f

// ---------------- scratch ----------------
__device__ float g_q   [(size_t)NTOK*NH*HD];
__device__ float g_k   [(size_t)NTOK*NKV*HD];
__device__ float g_v   [(size_t)NTOK*NKV*HD];
__device__ float g_hres[(size_t)NTOK*CC];
__device__ int   g_counts[EE];
__device__ int   g_tok [(size_t)EE*NTOK];
__device__ int   g_tidx[(size_t)NTOK*2];
__device__ int   g_tpos[(size_t)NTOK*2];
__device__ float g_twt [(size_t)NTOK*2];
__device__ float g_moe [(size_t)EE*NTOK*CC];
__device__ unsigned short g_hn16 [(size_t)NTOK*CC];
__device__ unsigned short g_att16[(size_t)NTOK*CC];
__device__ unsigned short g_gb16 [(size_t)NTOK*CC];
__device__ unsigned short g_hid16[(size_t)EE*NTOK*FF];
__device__ unsigned short g_w1t  [(size_t)EE*CC*FF];    // [e][FF][CC] bf16
__device__ unsigned short g_w3t  [(size_t)EE*CC*FF];
__device__ unsigned short g_w2t  [(size_t)EE*FF*CC];    // [e][CC][FF] bf16
__device__ unsigned short g_wqt  [(size_t)CC*NH*HD];    // [N][K] bf16
__device__ unsigned short g_wkt  [(size_t)CC*NKV*HD];
__device__ unsigned short g_wvt  [(size_t)CC*NKV*HD];
__device__ unsigned short g_wot  [(size_t)CC*CC];

// ---------------- helpers ----------------
__device__ __forceinline__ uint32_t smem_u32(const void* p) {
    uint32_t a;
    asm("{ .reg .u64 t; cvta.to.shared.u64 t, %1; cvt.u32.u64 %0, t; }" : "=r"(a) : "l"(p));
    return a;
}
__device__ __forceinline__ void cp16(uint32_t dst, const void* src) {
    asm volatile("cp.async.cg.shared.global [%0], [%1], 16;" :: "r"(dst), "l"(src));
}
__device__ __forceinline__ void cp_commit() { asm volatile("cp.async.commit_group;" ::: "memory"); }
__device__ __forceinline__ void cp_wait2() { asm volatile("cp.async.wait_group 2;" ::: "memory"); }
__device__ __forceinline__ void mma16(float* c, const uint32_t* a, const uint32_t* b) {
    asm volatile("mma.sync.aligned.m16n8k16.row.col.f32.bf16.bf16.f32 "
                 "{%0,%1,%2,%3}, {%4,%5,%6,%7}, {%8,%9}, {%0,%1,%2,%3};"
                 : "+f"(c[0]), "+f"(c[1]), "+f"(c[2]), "+f"(c[3])
                 : "r"(a[0]), "r"(a[1]), "r"(a[2]), "r"(a[3]), "r"(b[0]), "r"(b[1]));
}
__device__ __forceinline__ void ldsm4(uint32_t* r, uint32_t addr) {
    asm volatile("ldmatrix.sync.aligned.m8n8.x4.shared.b16 {%0,%1,%2,%3}, [%4];"
                 : "=r"(r[0]), "=r"(r[1]), "=r"(r[2]), "=r"(r[3]) : "r"(addr));
}

// ================= bf16 GEMM core (ldmatrix) =================
#define HROW 80
#define HTILE_B (128*HROW)
#define NS16 4
#define SMEM16 (NS16*2*HTILE_B)    // 81920 bytes

struct Bf16Loop {
    uint32_t sbase;
    int lane, wm, wn;
    uint32_t aR, aK, bR, bK;
    __device__ __forceinline__ void init(uint32_t sb, int tid) {
        sbase = sb;
        lane = tid & 31;
        int warp = tid >> 5;
        wm = warp & 3; wn = warp >> 2;
        aR = (lane & 7) + ((lane >> 3) & 1) * 8;
        aK = ((lane >> 4) & 1) * 16;
        bR = (lane & 7) + ((lane >> 4) & 1) * 8;
        bK = ((lane >> 3) & 1) * 16;
    }
    __device__ __forceinline__ void compute(int p, float acc[2][8][4]) {
        uint32_t Am = sbase + p * (2 * HTILE_B);
        uint32_t Bm = Am + HTILE_B;
        #pragma unroll
        for (int kk = 0; kk < 2; kk++) {
            uint32_t a[2][4], b[4][4];
            #pragma unroll
            for (int mi = 0; mi < 2; mi++)
                ldsm4(a[mi], Am + (wm * 32 + mi * 16 + aR) * HROW + kk * 32 + aK);
            #pragma unroll
            for (int p2 = 0; p2 < 4; p2++)
                ldsm4(b[p2], Bm + (wn * 64 + p2 * 16 + bR) * HROW + kk * 32 + bK);
            #pragma unroll
            for (int mi = 0; mi < 2; mi++)
                #pragma unroll
                for (int ni = 0; ni < 8; ni++)
                    mma16(acc[mi][ni], a[mi], &b[ni >> 1][(ni & 1) * 2]);
        }
    }
};

// dense bf16 GEMM body: C(f32)[m][nloc..] = A16[m][K] @ Wt16[n][K]^T (+res)
__device__ __forceinline__ void gemm_body_bf16(
    const unsigned short* __restrict__ A, const unsigned short* __restrict__ Wt,
    float* __restrict__ C, const float* __restrict__ res,
    int K, int Nw, int m0, int nloc, char* smraw)
{
    int tid = threadIdx.x;
    uint32_t sbase = smem_u32(smraw);
    Bf16Loop L; L.init(sbase, tid);

    int row = tid >> 1, sl = (tid & 1) * 2;
    const unsigned short* arow = A + (size_t)(m0 + row) * K;
    const unsigned short* brow = Wt + (size_t)(nloc + row) * K;

    uint32_t aD[NS16], bD[NS16];
    #pragma unroll
    for (int s = 0; s < NS16; s++) {
        aD[s] = sbase + s * (2 * HTILE_B) + row * HROW + sl * 16;
        bD[s] = aD[s] + HTILE_B;
    }
    auto load_chunk = [&](int ci, int p) {
        const unsigned short* as = arow + ci * 32 + sl * 8;
        cp16(aD[p], as); cp16(aD[p] + 16, as + 8);
        const unsigned short* bs = brow + ci * 32 + sl * 8;
        cp16(bD[p], bs); cp16(bD[p] + 16, bs + 8);
    };

    float acc[2][8][4];
    #pragma unroll
    for (int mi = 0; mi < 2; mi++)
        #pragma unroll
        for (int ni = 0; ni < 8; ni++)
            #pragma unroll
            for (int q = 0; q < 4; q++) acc[mi][ni][q] = 0.f;

    int NC = K / 32;
    load_chunk(0, 0); cp_commit();
    load_chunk(1, 1); cp_commit();
    load_chunk(2, 2); cp_commit();
    for (int i = 0; i < NC; i++) {
        cp_wait2();
        __syncthreads();
        int nx = i + NS16 - 1;
        if (nx < NC) load_chunk(nx, nx % NS16);
        cp_commit();
        L.compute(i % NS16, acc);
    }

    int lr = L.lane >> 2, lc = L.lane & 3;
    #pragma unroll
    for (int mi = 0; mi < 2; mi++)
        #pragma unroll
        for (int half = 0; half < 2; half++) {
            int m = m0 + L.wm * 32 + mi * 16 + half * 8 + lr;
            float* crow = C + (size_t)m * Nw + nloc + L.wn * 64;
            #pragma unroll
            for (int ni = 0; ni < 8; ni++) {
                float c0 = acc[mi][ni][half * 2 + 0];
                float c1 = acc[mi][ni][half * 2 + 1];
                if (res) {
                    const float2 rr = *(const float2*)(res + (size_t)m * Nw + nloc + L.wn * 64 + ni * 8 + lc * 2);
                    c0 += rr.x; c1 += rr.y;
                }
                float2 v; v.x = c0; v.y = c1;
                *(float2*)(crow + ni * 8 + lc * 2) = v;
            }
        }
}

// fused QKV (bf16)
__global__ __launch_bounds__(256, 2)
void qkv16_gemm()
{
    extern __shared__ char smraw[];
    int m0 = blockIdx.y * 128;
    int nb = blockIdx.x;
    const unsigned short* Wt; float* O; int Nw, nloc;
    if (nb < 8)       { Wt = g_wqt; O = g_q; Nw = NH * HD;  nloc = nb * 128; }
    else if (nb < 10) { Wt = g_wkt; O = g_k; Nw = NKV * HD; nloc = (nb - 8) * 128; }
    else              { Wt = g_wvt; O = g_v; Nw = NKV * HD; nloc = (nb - 10) * 128; }
    gemm_body_bf16(g_hn16, Wt, O, (const float*)0, CC, Nw, m0, nloc, smraw);
}

// wo projection + residual (bf16)
__global__ __launch_bounds__(256, 2)
void wo16_gemm(const float* __restrict__ res)
{
    extern __shared__ char smraw[];
    gemm_body_bf16(g_att16, g_wot, g_hres, res, CC, CC,
                   blockIdx.y * 128, blockIdx.x * 128, smraw);
}

// ---- fused MoE pass 1+2 (n-block fastest) ----
__global__ __launch_bounds__(256, 2)
void moe13_fused()
{
    int e = blockIdx.z;
    int cnt = g_counts[e];
    int m0 = blockIdx.y * 128;
    if (m0 >= cnt) return;
    int c0 = blockIdx.x * 64;

    extern __shared__ char smraw[];
    int tid = threadIdx.x;
    uint32_t sbase = smem_u32(smraw);
    Bf16Loop L; L.init(sbase, tid);

    int row = tid >> 1, sl = (tid & 1) * 2;
    const unsigned short* arow;
    {
        int grow = m0 + row;
        int g2 = (grow < cnt) ? grow : 0;
        arow = g_gb16 + (size_t)g_tok[e * NTOK + g2] * CC;
    }
    const unsigned short* brow = (row < 64)
        ? g_w1t + (size_t)e * CC * FF + (size_t)(c0 + row) * CC
        : g_w3t + (size_t)e * CC * FF + (size_t)(c0 + row - 64) * CC;

    uint32_t aD[NS16], bD[NS16];
    #pragma unroll
    for (int s = 0; s < NS16; s++) {
        aD[s] = sbase + s * (2 * HTILE_B) + row * HROW + sl * 16;
        bD[s] = aD[s] + HTILE_B;
    }
    auto load_chunk = [&](int ci, int p) {
        const unsigned short* as = arow + ci * 32 + sl * 8;
        cp16(aD[p], as); cp16(aD[p] + 16, as + 8);
        const unsigned short* bs = brow + ci * 32 + sl * 8;
        cp16(bD[p], bs); cp16(bD[p] + 16, bs + 8);
    };

    float acc[2][8][4];
    #pragma unroll
    for (int mi = 0; mi < 2; mi++)
        #pragma unroll
        for (int ni = 0; ni < 8; ni++)
            #pragma unroll
            for (int q = 0; q < 4; q++) acc[mi][ni][q] = 0.f;

    const int NC = CC / 32;
    load_chunk(0, 0); cp_commit();
    load_chunk(1, 1); cp_commit();
    load_chunk(2, 2); cp_commit();
    for (int i = 0; i < NC; i++) {
        cp_wait2();
        __syncthreads();
        int nx = i + NS16 - 1;
        if (nx < NC) load_chunk(nx, nx % NS16);
        cp_commit();
        L.compute(i % NS16, acc);
    }

    __syncthreads();
    float* eps = (float*)smraw;
    int lr = L.lane >> 2, lc = L.lane & 3;
    if (L.wn == 1) {
        #pragma unroll
        for (int mi = 0; mi < 2; mi++)
            #pragma unroll
            for (int half = 0; half < 2; half++) {
                int ml = L.wm * 32 + mi * 16 + half * 8 + lr;
                #pragma unroll
                for (int ni = 0; ni < 8; ni++) {
                    eps[ml * 66 + ni * 8 + lc * 2 + 0] = acc[mi][ni][half * 2 + 0];
                    eps[ml * 66 + ni * 8 + lc * 2 + 1] = acc[mi][ni][half * 2 + 1];
                }
            }
    }
    __syncthreads();
    if (L.wn == 0) {
        unsigned short* hrow = g_hid16 + (size_t)e * NTOK * FF + c0;
        #pragma unroll
        for (int mi = 0; mi < 2; mi++)
            #pragma unroll
            for (int half = 0; half < 2; half++) {
                int ml = L.wm * 32 + mi * 16 + half * 8 + lr;
                int m = m0 + ml;
                if (m < cnt) {
                    #pragma unroll
                    for (int ni = 0; ni < 8; ni++) {
                        float x0 = acc[mi][ni][half * 2 + 0];
                        float x1 = acc[mi][ni][half * 2 + 1];
                        float a3x = eps[ml * 66 + ni * 8 + lc * 2 + 0];
                        float a3y = eps[ml * 66 + ni * 8 + lc * 2 + 1];
                        float v0 = x0 / (1.f + __expf(-x0)) * a3x;
                        float v1 = x1 / (1.f + __expf(-x1)) * a3y;
                        __nv_bfloat162 o(__float2bfloat16_rn(v0), __float2bfloat16_rn(v1));
                        *(__nv_bfloat162*)(hrow + (size_t)m * FF + ni * 8 + lc * 2) = o;
                    }
                }
            }
    }
}

// ---- MoE pass 3 ----
__global__ __launch_bounds__(256, 2)
void moe2_gemm()
{
    int e = blockIdx.z;
    int cnt = g_counts[e];
    int m0 = blockIdx.y * 128;
    if (m0 >= cnt) return;
    int n0 = blockIdx.x * 128;

    extern __shared__ char smraw[];
    int tid = threadIdx.x;
    uint32_t sbase = smem_u32(smraw);
    Bf16Loop L; L.init(sbase, tid);

    int row = tid >> 1, sl = (tid & 1) * 2;
    const unsigned short* arow = g_hid16 + (size_t)e * NTOK * FF + (size_t)(m0 + row) * FF;
    const unsigned short* brow = g_w2t + (size_t)e * FF * CC + (size_t)(n0 + row) * FF;

    uint32_t aD[NS16], bD[NS16];
    #pragma unroll
    for (int s = 0; s < NS16; s++) {
        aD[s] = sbase + s * (2 * HTILE_B) + row * HROW + sl * 16;
        bD[s] = aD[s] + HTILE_B;
    }
    auto load_chunk = [&](int ci, int p) {
        const unsigned short* as = arow + ci * 32 + sl * 8;
        cp16(aD[p], as); cp16(aD[p] + 16, as + 8);
        const unsigned short* bs = brow + ci * 32 + sl * 8;
        cp16(bD[p], bs); cp16(bD[p] + 16, bs + 8);
    };

    float acc[2][8][4];
    #pragma unroll
    for (int mi = 0; mi < 2; mi++)
        #pragma unroll
        for (int ni = 0; ni < 8; ni++)
            #pragma unroll
            for (int q = 0; q < 4; q++) acc[mi][ni][q] = 0.f;

    const int NC = FF / 32;
    load_chunk(0, 0); cp_commit();
    load_chunk(1, 1); cp_commit();
    load_chunk(2, 2); cp_commit();
    for (int i = 0; i < NC; i++) {
        cp_wait2();
        __syncthreads();
        int nx = i + NS16 - 1;
        if (nx < NC) load_chunk(nx, nx % NS16);
        cp_commit();
        L.compute(i % NS16, acc);
    }

    int lr = L.lane >> 2, lc = L.lane & 3;
    float* Co = g_moe + (size_t)e * NTOK * CC;
    #pragma unroll
    for (int mi = 0; mi < 2; mi++)
        #pragma unroll
        for (int half = 0; half < 2; half++) {
            int m = m0 + L.wm * 32 + mi * 16 + half * 8 + lr;
            if (m < cnt) {
                #pragma unroll
                for (int ni = 0; ni < 8; ni++) {
                    float2 v;
                    v.x = acc[mi][ni][half * 2 + 0];
                    v.y = acc[mi][ni][half * 2 + 1];
                    *(float2*)(Co + (size_t)m * CC + n0 + L.wn * 64 + ni * 8 + lc * 2) = v;
                }
            }
        }
}

// ---------------- weight transpose+convert (all weights, + zero counts) ----------------
__global__ void transpose_all(const float* __restrict__ w1, const float* __restrict__ w3,
                              const float* __restrict__ w2, const float* __restrict__ wq,
                              const float* __restrict__ wk, const float* __restrict__ wv,
                              const float* __restrict__ wo) {
    if (blockIdx.x == 0 && blockIdx.z == 0 && threadIdx.x < EE)
        g_counts[threadIdx.x] = 0;
    __shared__ float t[32][33];
    int z = blockIdx.z;
    const float* src; unsigned short* dst; int K, N;
    if (z < 8)       { src = w1 + (size_t)z * CC * FF;        dst = g_w1t + (size_t)z * CC * FF;        K = CC; N = FF; }
    else if (z < 16) { src = w3 + (size_t)(z - 8) * CC * FF;  dst = g_w3t + (size_t)(z - 8) * CC * FF;  K = CC; N = FF; }
    else if (z < 24) { src = w2 + (size_t)(z - 16) * FF * CC; dst = g_w2t + (size_t)(z - 16) * FF * CC; K = FF; N = CC; }
    else if (z == 24){ src = wq; dst = g_wqt; K = CC; N = NH * HD; }
    else if (z == 25){ src = wk; dst = g_wkt; K = CC; N = NKV * HD; }
    else if (z == 26){ src = wv; dst = g_wvt; K = CC; N = NKV * HD; }
    else             { src = wo; dst = g_wot; K = CC; N = CC; }
    int nb = N / 32;
    int tot = (K / 32) * nb;
    if ((int)blockIdx.x >= tot) return;
    int n0 = (blockIdx.x % nb) * 32;
    int k0 = (blockIdx.x / nb) * 32;
    int tx = threadIdx.x & 31, ty = threadIdx.x >> 5;
    #pragma unroll
    for (int p = 0; p < 4; p++)
        t[ty + p * 8][tx] = src[(size_t)(k0 + ty + p * 8) * N + n0 + tx];
    __syncthreads();
    #pragma unroll
    for (int p = 0; p < 4; p++) {
        __nv_bfloat16 v = __float2bfloat16_rn(t[tx][ty + p * 8]);
        dst[(size_t)(n0 + ty + p * 8) * K + k0 + tx] = *(unsigned short*)&v;
    }
}

// ---------------- rmsnorm (+ optional fused MoE routing) ----------------
__global__ void rmsnorm_kernel(const float* __restrict__ x,
                               const float* __restrict__ w,
                               unsigned short* __restrict__ o16,
                               const float* __restrict__ gw) {
    int row = blockIdx.x;
    const float* xr = x + (size_t)row * CC;
    __shared__ float red[8];
    __shared__ float gred[8][EE];
    float s = 0.f;
    for (int c = threadIdx.x; c < CC; c += 256) { float v = xr[c]; s += v * v; }
    #pragma unroll
    for (int off = 16; off; off >>= 1) s += __shfl_xor_sync(~0u, s, off);
    if ((threadIdx.x & 31) == 0) red[threadIdx.x >> 5] = s;
    __syncthreads();
    if (threadIdx.x < 8) {
        float t = red[threadIdx.x];
        #pragma unroll
        for (int off = 4; off; off >>= 1) t += __shfl_xor_sync(0xff, t, off);
        if (threadIdx.x == 0) red[0] = t;
    }
    __syncthreads();
    float inv = rsqrtf(red[0] * (1.0f / CC) + EPS);
    float la[EE];
    #pragma unroll
    for (int e = 0; e < EE; e++) la[e] = 0.f;
    for (int c = threadIdx.x; c < CC; c += 256) {
        float v = xr[c] * inv * w[c];
        __nv_bfloat16 h = __float2bfloat16_rn(v);
        o16[(size_t)row * CC + c] = *(unsigned short*)&h;
        if (gw) {
            #pragma unroll
            for (int e = 0; e < EE; e++) la[e] += v * gw[c * EE + e];
        }
    }
    if (gw) {
        #pragma unroll
        for (int e = 0; e < EE; e++)
            #pragma unroll
            for (int off = 16; off; off >>= 1)
                la[e] += __shfl_xor_sync(~0u, la[e], off);
        if ((threadIdx.x & 31) == 0) {
            #pragma unroll
            for (int e = 0; e < EE; e++) gred[threadIdx.x >> 5][e] = la[e];
        }
        __syncthreads();
        if (threadIdx.x == 0) {
            float acc[EE];
            #pragma unroll
            for (int e = 0; e < EE; e++) {
                float t = 0.f;
                #pragma unroll
                for (int wq2 = 0; wq2 < 8; wq2++) t += gred[wq2][e];
                acc[e] = t;
            }
            int i0 = 0;
            #pragma unroll
            for (int e = 1; e < EE; e++) if (acc[e] > acc[i0]) i0 = e;
            int i1 = -1;
            #pragma unroll
            for (int e = 0; e < EE; e++)
                if (e != i0 && (i1 < 0 || acc[e] > acc[i1])) i1 = e;
            float p1 = __expf(acc[i1] - acc[i0]);
            float sw = 1.0f + p1;
            float w0 = 1.0f / sw, w1 = p1 / sw;
            int pos0 = atomicAdd(&g_counts[i0], 1);
            int pos1 = atomicAdd(&g_counts[i1], 1);
            g_tok[i0 * NTOK + pos0] = row;
            g_tok[i1 * NTOK + pos1] = row;
            g_tidx[row * 2 + 0] = i0; g_tidx[row * 2 + 1] = i1;
            g_tpos[row * 2 + 0] = pos0; g_tpos[row * 2 + 1] = pos1;
            g_twt [row * 2 + 0] = w0;  g_twt [row * 2 + 1] = w1;
        }
    }
}

__global__ void rope_all_kernel(float* __restrict__ q, float* __restrict__ k) {
    int idx = blockIdx.x * blockDim.x + threadIdx.x;
    const int qtot = NTOK * NH * 32;
    const int ktot = NTOK * NKV * 32;
    float* t; int nh;
    if (idx < qtot) { t = q; nh = NH; }
    else { idx -= qtot; if (idx >= ktot) return; t = k; nh = NKV; }
    int n = idx / (nh * 32);
    int r = idx - n * (nh * 32);
    int h = r >> 5;
    int d = r & 31;
    int pos = n & (TT - 1);
    float* p = t + ((size_t)n * nh + h) * HD;
    float fr  = __powf(10000.0f, -(float)d * (1.0f / 32.0f));
    float ang = (float)pos * fr;
    float cs = cosf(ang), sn = sinf(ang);
    float x1 = p[d], x2 = p[d + 32];
    p[d]      = x1 * cs - x2 * sn;
    p[d + 32] = x2 * cs + x1 * sn;
}

// ---------------- tensor-core flash attention (bf16 ldmatrix) ----------------
// block: 128 q rows of one (b,h); 4 warps, each owns 32 q rows.
// QS [q][d] stride 160B; KS [j][d] stride 160B; VS [d][j] stride 80B; PS [q][j] stride 80B
__global__ __launch_bounds__(128, 2)
void attn_mma(const float* __restrict__ q, const float* __restrict__ k,
              const float* __restrict__ v)
{
    __shared__ unsigned short QS[128 * 80];   // 80 ushort/row = 160 B
    __shared__ unsigned short KS[32 * 80];
    __shared__ unsigned short VS[64 * 40];    // 40 ushort/row = 80 B
    __shared__ unsigned short PS[4][32 * 40];

    int bh = blockIdx.y;
    int b = bh >> 4, h = bh & 15;
    int kh = h >> 2;
    int q0 = blockIdx.x * 128;
    int tid = threadIdx.x;
    int warp = tid >> 5, lane = tid & 31;
    int lr = lane >> 2, lc = lane & 3;
    int qw = q0 + warp * 32;

    uint32_t sQ = smem_u32(QS), sK = smem_u32(KS), sV = smem_u32(VS), sP = smem_u32(PS[warp]);
    uint32_t aR = (lane & 7) + ((lane >> 3) & 1) * 8;
    uint32_t aK = ((lane >> 4) & 1) * 16;
    uint32_t bR = (lane & 7) + ((lane >> 4) & 1) * 8;
    uint32_t bK = ((lane >> 3) & 1) * 16;

    // ---- stage Q once (scaled, bf16): 2 half-rows per thread -> all 128 rows ----
    #pragma unroll
    for (int rr = 0; rr < 2; rr++) {
        int row = (tid >> 1) + rr * 64;
        int half = (tid & 1) * 32;
        const float* qrow = q + ((size_t)(b * TT + q0 + row) * NH + h) * HD + half;
        unsigned short* dst = QS + row * 80 + half;
        #pragma unroll
        for (int i = 0; i < 8; i++) {
            float4 f = *(const float4*)(qrow + i * 4);
            __nv_bfloat162 p0(__float2bfloat16_rn(f.x * 0.125f), __float2bfloat16_rn(f.y * 0.125f));
            __nv_bfloat162 p1(__float2bfloat16_rn(f.z * 0.125f), __float2bfloat16_rn(f.w * 0.125f));
            *(__nv_bfloat162*)(dst + i * 4)     = p0;
            *(__nv_bfloat162*)(dst + i * 4 + 2) = p1;
        }
    }
    __syncthreads();

    // Q fragments in registers (constant across chunks)
    uint32_t Qf[2][4][4];
    #pragma unroll
    for (int mi = 0; mi < 2; mi++)
        #pragma unroll
        for (int kk = 0; kk < 4; kk++)
            ldsm4(Qf[mi][kk], sQ + (warp * 32 + mi * 16 + aR) * 160 + kk * 32 + aK);

    float O[2][8][4];
    #pragma unroll
    for (int mi = 0; mi < 2; mi++)
        #pragma unroll
        for (int ni = 0; ni < 8; ni++)
            #pragma unroll
            for (int c = 0; c < 4; c++) O[mi][ni][c] = 0.f;
    float mrow[2][2] = { {-1e30f, -1e30f}, {-1e30f, -1e30f} };
    float lrow[2][2] = { {0.f, 0.f}, {0.f, 0.f} };

    int kmin = q0 - WIN + 1; if (kmin < 0) kmin = 0;
    kmin &= ~31;
    int kmax = q0 + 127;

    for (int kt = kmin; kt <= kmax; kt += 32) {
        __syncthreads();
        // stage K [j][d] bf16 (4 threads/row)
        {
            int j = tid >> 2, part = (tid & 3) * 16;
            const float* krow = k + ((size_t)(b * TT + kt + j) * NKV + kh) * HD + part;
            unsigned short* dst = KS + j * 80 + part;
            #pragma unroll
            for (int i = 0; i < 4; i++) {
                float4 f = *(const float4*)(krow + i * 4);
                __nv_bfloat162 p0(__float2bfloat16_rn(f.x), __float2bfloat16_rn(f.y));
                __nv_bfloat162 p1(__float2bfloat16_rn(f.z), __float2bfloat16_rn(f.w));
                *(__nv_bfloat162*)(dst + i * 4)     = p0;
                *(__nv_bfloat162*)(dst + i * 4 + 2) = p1;
            }
        }
        // stage V transposed [d][j] bf16
        {
            int j = tid & 31, dg = (tid >> 5) * 16;
            const float* vrow = v + ((size_t)(b * TT + kt + j) * NKV + kh) * HD + dg;
            #pragma unroll
            for (int i = 0; i < 4; i++) {
                float4 f = *(const float4*)(vrow + i * 4);
                int d0 = dg + i * 4;
                __nv_bfloat16 b0 = __float2bfloat16_rn(f.x);
                __nv_bfloat16 b1 = __float2bfloat16_rn(f.y);
                __nv_bfloat16 b2 = __float2bfloat16_rn(f.z);
                __nv_bfloat16 b3 = __float2bfloat16_rn(f.w);
                VS[(d0 + 0) * 40 + j] = *(unsigned short*)&b0;
                VS[(d0 + 1) * 40 + j] = *(unsigned short*)&b1;
                VS[(d0 + 2) * 40 + j] = *(unsigned short*)&b2;
                VS[(d0 + 3) * 40 + j] = *(unsigned short*)&b3;
            }
        }
        __syncthreads();

        // ---- S = Q K^T ----
        float S[2][4][4];
        #pragma unroll
        for (int mi = 0; mi < 2; mi++)
            #pragma unroll
            for (int nj = 0; nj < 4; nj++)
                #pragma unroll
                for (int c = 0; c < 4; c++) S[mi][nj][c] = 0.f;
        #pragma unroll
        for (int kk = 0; kk < 4; kk++) {
            uint32_t bf[2][4];
            ldsm4(bf[0], sK + bR * 160 + kk * 32 + bK);
            ldsm4(bf[1], sK + (16 + bR) * 160 + kk * 32 + bK);
            #pragma unroll
            for (int mi = 0; mi < 2; mi++)
                #pragma unroll
                for (int nj = 0; nj < 4; nj++)
                    mma16(S[mi][nj], Qf[mi][kk], &bf[nj >> 1][(nj & 1) * 2]);
        }

        // ---- mask + online softmax + stage P (bf16) ----
        #pragma unroll
        for (int mi = 0; mi < 2; mi++) {
            #pragma unroll
            for (int h2 = 0; h2 < 2; h2++) {
                int qi = qw + mi * 16 + h2 * 8 + lr;
                float tm = -1e30f;
                #pragma unroll
                for (int nj = 0; nj < 4; nj++) {
                    #pragma unroll
                    for (int c = 0; c < 2; c++) {
                        int j = kt + nj * 8 + lc * 2 + c;
                        bool ok = (j <= qi) && (j > qi - WIN);
                        float sv = ok ? S[mi][nj][h2 * 2 + c] : -1e30f;
                        S[mi][nj][h2 * 2 + c] = sv;
                        tm = fmaxf(tm, sv);
                    }
                }
                tm = fmaxf(tm, __shfl_xor_sync(~0u, tm, 1));
                tm = fmaxf(tm, __shfl_xor_sync(~0u, tm, 2));
                float mn = fmaxf(mrow[mi][h2], tm);
                float corr = __expf(mrow[mi][h2] - mn);
                #pragma unroll
                for (int ni = 0; ni < 8; ni++) {
                    O[mi][ni][h2 * 2 + 0] *= corr;
                    O[mi][ni][h2 * 2 + 1] *= corr;
                }
                float ls = 0.f;
                unsigned short* prow = PS[warp] + (mi * 16 + h2 * 8 + lr) * 40;
                #pragma unroll
                for (int nj = 0; nj < 4; nj++) {
                    float sv0 = S[mi][nj][h2 * 2 + 0];
                    float sv1 = S[mi][nj][h2 * 2 + 1];
                    float p0 = (sv0 > -9e29f) ? __expf(sv0 - mn) : 0.f;
                    float p1 = (sv1 > -9e29f) ? __expf(sv1 - mn) : 0.f;
                    ls += p0 + p1;
                    __nv_bfloat162 pp(__float2bfloat16_rn(p0), __float2bfloat16_rn(p1));
                    *(__nv_bfloat162*)(prow + nj * 8 + lc * 2) = pp;
                }
                ls += __shfl_xor_sync(~0u, ls, 1);
                ls += __shfl_xor_sync(~0u, ls, 2);
                lrow[mi][h2] = lrow[mi][h2] * corr + ls;
                mrow[mi][h2] = mn;
            }
        }
        __syncwarp();

        // ---- O += P V ----
        #pragma unroll
        for (int kk2 = 0; kk2 < 2; kk2++) {
            uint32_t a[2][4], bfv[4][4];
            #pragma unroll
            for (int mi = 0; mi < 2; mi++)
                ldsm4(a[mi], sP + (mi * 16 + aR) * 80 + kk2 * 32 + aK);
            #pragma unroll
            for (int dt = 0; dt < 4; dt++)
                ldsm4(bfv[dt], sV + (dt * 16 + bR) * 80 + kk2 * 32 + bK);
            #pragma unroll
            for (int mi = 0; mi < 2; mi++)
                #pragma unroll
                for (int ni = 0; ni < 8; ni++)
                    mma16(O[mi][ni], a[mi], &bfv[ni >> 1][(ni & 1) * 2]);
        }
    }

    // ---- epilogue: write att as bf16 for the wo GEMM ----
    #pragma unroll
    for (int mi = 0; mi < 2; mi++) {
        #pragma unroll
        for (int h2 = 0; h2 < 2; h2++) {
            int qi = qw + mi * 16 + h2 * 8 + lr;
            float inv = 1.f / lrow[mi][h2];
            unsigned short* orow = g_att16 + ((size_t)(b * TT + qi) * NH + h) * HD;
            #pragma unroll
            for (int ni = 0; ni < 8; ni++) {
                float vx = O[mi][ni][h2 * 2 + 0] * inv;
                float vy = O[mi][ni][h2 * 2 + 1] * inv;
                __nv_bfloat162 o(__float2bfloat16_rn(vx), __float2bfloat16_rn(vy));
                *(__nv_bfloat162*)(orow + ni * 8 + lc * 2) = o;
            }
        }
    }
}

// ---------------- final combine ----------------
__global__ void combine_kernel(float* __restrict__ out) {
    int idx = blockIdx.x * blockDim.x + threadIdx.x;
    int n  = idx >> 8;
    int c4 = idx & 255;
    int e0 = g_tidx[n * 2], e1 = g_tidx[n * 2 + 1];
    int p0 = g_tpos[n * 2], p1 = g_tpos[n * 2 + 1];
    float w0 = g_twt[n * 2], w1 = g_twt[n * 2 + 1];
    float4 h4 = ((const float4*)g_hres)[idx];
    float4 a = ((const float4*)(g_moe + ((size_t)e0 * NTOK + p0) * CC))[c4];
    float4 b = ((const float4*)(g_moe + ((size_t)e1 * NTOK + p1) * CC))[c4];
    float4 o;
    o.x = h4.x + w0 * a.x + w1 * b.x;
    o.y = h4.y + w0 * a.y + w1 * b.y;
    o.z = h4.z + w0 * a.z + w1 * b.z;
    o.w = h4.w + w0 * a.w + w1 * b.w;
    ((float4*)out)[idx] = o;
}

// ---------------- launch ----------------
extern "C" void kernel_launch(void* const* d_in, const int* in_sizes, int n_in,
                              void* d_out, int out_size) {
    const float* x           = (const float*)d_in[0];
    const float* attn_norm_w = (const float*)d_in[1];
    const float* ffn_norm_w  = (const float*)d_in[2];
    const float* wq          = (const float*)d_in[3];
    const float* wk          = (const float*)d_in[4];
    const float* wv          = (const float*)d_in[5];
    const float* wo          = (const float*)d_in[6];
    const float* gate_w      = (const float*)d_in[7];
    const float* w1          = (const float*)d_in[8];
    const float* w2          = (const float*)d_in[9];
    const float* w3          = (const float*)d_in[10];
    float* out = (float*)d_out;

    cudaFuncSetAttribute(qkv16_gemm,  cudaFuncAttributeMaxDynamicSharedMemorySize, SMEM16);
    cudaFuncSetAttribute(wo16_gemm,   cudaFuncAttributeMaxDynamicSharedMemorySize, SMEM16);
    cudaFuncSetAttribute(moe13_fused, cudaFuncAttributeMaxDynamicSharedMemorySize, SMEM16);
    cudaFuncSetAttribute(moe2_gemm,   cudaFuncAttributeMaxDynamicSharedMemorySize, SMEM16);

    float *qb, *kb, *vb;
    unsigned short *hn16, *gb16;
    cudaGetSymbolAddress((void**)&qb,    g_q);
    cudaGetSymbolAddress((void**)&kb,    g_k);
    cudaGetSymbolAddress((void**)&vb,    g_v);
    cudaGetSymbolAddress((void**)&hn16,  g_hn16);
    cudaGetSymbolAddress((void**)&gb16,  g_gb16);

    float* hres;
    cudaGetSymbolAddress((void**)&hres, g_hres);

    // 1: weight transpose+convert (all weights, + zero counts)
    transpose_all<<<dim3(4096, 1, 28), 256>>>(w1, w3, w2, wq, wk, wv, wo);
    // 2: attn rmsnorm (bf16 out)
    rmsnorm_kernel<<<NTOK, 256>>>(x, attn_norm_w, hn16, nullptr);
    // 3: fused QKV projections (bf16)
    qkv16_gemm<<<dim3(12, 32), 256, SMEM16>>>();
    // 4: RoPE
    {
        int tot = NTOK * (NH + NKV) * 32;
        rope_all_kernel<<<(tot + 255) / 256, 256>>>(qb, kb);
    }
    // 5: bf16 tensor-core sliding-window attention (emits bf16 att)
    attn_mma<<<dim3(TT / 128, BB * NH), 128>>>(qb, kb, vb);
    // 6: output projection + residual (bf16)
    wo16_gemm<<<dim3(8, 32), 256, SMEM16>>>(x);
    // 7: ffn rmsnorm + fused routing
    rmsnorm_kernel<<<NTOK, 256>>>(hres, ffn_norm_w, gb16, gate_w);
    // 8: fused MoE pass 1+2
    moe13_fused<<<dim3(FF / 64, NTOK / 128, EE), 256, SMEM16>>>();
    // 9: MoE pass 3
    moe2_gemm<<<dim3(CC / 128, NTOK / 128, EE), 256, SMEM16>>>();
    // 10: final combine + residual
    combine_kernel<<<(NTOK * CC / 4) / 256, 256>>>(out);
}